// round 12
// baseline (speedup 1.0000x reference)
#include <cuda_runtime.h>
#include <cuda_fp16.h>
#include <math.h>
#include <stdint.h>

// ---------------------------------------------------------------------------
// Problem constants
// ---------------------------------------------------------------------------
#define BATCH   4
#define HW      4096
#define BN_EPS  1e-5f
#define VPIX    5440
#define VSTRF   (VPIX*256)
#define WROW    512                  // split row: [256 hi][256 lo] fp16
#define AROW    256                  // plain activation row: 256 fp16

__device__ __constant__ int c_voff[4] = {0, 1048576, 1310720, 1376256};
__device__ __constant__ int c_vpix[4] = {0, 4096, 5120, 5376};
__device__ __constant__ int c_mact[4] = {4096, 1024, 256, 64};
__device__ __constant__ int c_vts[5]  = {0, 32, 40, 42, 43};
__device__ __constant__ int c_ftk[5]  = {0, 128, 160, 168, 170};
__constant__ float G4[4][3] = {{1.f,0.f,0.f},{0.5f,0.5f,0.5f},
                               {0.5f,-0.5f,0.5f},{0.f,0.f,1.f}};

// ---------------------------------------------------------------------------
// Scratch
// ---------------------------------------------------------------------------
__device__ __half g_fT [BATCH * VPIX * AROW];      // feats fp16 (hi only)
__device__ __half g_att[BATCH * HW * AROW];        // sampler out fp16
__device__ __half g_qwT[256 * WROW];               // q_w^T split
__device__ __half g_vw [4 * 256 * WROW];           // v_w split
__device__ __half g_ow [256 * WROW];               // out_w split
__device__ __half g_W2 [16 * 384 * WROW];          // G-transformed conv w split
__device__ __half g_Uw [16 * 384 * WROW];          // winograd weights split
__device__ __half g_V  [16L * 4 * 1024 * WROW];    // winograd input transform SPLIT
__device__ float g_M  [16L * 4 * 1024 * 384];      // winograd GEMM out fp32
__device__ __half g_v  [BATCH * VSTRF];            // values fp16 channel-last
__device__ float g_cb [384];
__device__ float g_bns[256], g_bnb[256];

// ---------------------------------------------------------------------------
// Helpers
// ---------------------------------------------------------------------------
__device__ __forceinline__ uint32_t smem_u32(const void* p) {
    uint32_t a;
    asm("{ .reg .u64 t; cvta.to.shared.u64 t, %1; cvt.u32.u64 %0, t; }"
        : "=r"(a) : "l"(p));
    return a;
}
__device__ __forceinline__ void cp16(uint32_t dst, const void* src, bool v) {
    int sz = v ? 16 : 0;
    asm volatile("cp.async.cg.shared.global [%0], [%1], 16, %2;\n"
                 :: "r"(dst), "l"(src), "r"(sz) : "memory");
}
__device__ __forceinline__ void cp_commit() {
    asm volatile("cp.async.commit_group;\n" ::: "memory");
}
__device__ __forceinline__ void cp_wait1() {
    asm volatile("cp.async.wait_group 1;\n" ::: "memory");
}
__device__ __forceinline__ void mma_f16(float* c, const uint32_t* a, const uint32_t* b) {
    asm volatile(
        "mma.sync.aligned.m16n8k16.row.col.f32.f16.f16.f32 "
        "{%0,%1,%2,%3}, {%4,%5,%6,%7}, {%8,%9}, {%0,%1,%2,%3};"
        : "+f"(c[0]), "+f"(c[1]), "+f"(c[2]), "+f"(c[3])
        : "r"(a[0]), "r"(a[1]), "r"(a[2]), "r"(a[3]), "r"(b[0]), "r"(b[1]));
}
#define LDSM_X4(r0, r1, r2, r3, addr) \
    asm volatile("ldmatrix.sync.aligned.m8n8.x4.shared.b16 {%0,%1,%2,%3}, [%4];" \
        : "=r"(r0), "=r"(r1), "=r"(r2), "=r"(r3) : "r"(addr))

__device__ __forceinline__ void split_h(float x, __half& h, __half& l) {
    h = __float2half_rn(x);
    l = __float2half_rn(x - __half2float(h));
}

#define STG_B    16384
#define DSMEM_SZ (6 * STG_B)          // 96 KB -> 2 CTAs/SM

// ---------------------------------------------------------------------------
// Unified fp16 GEMM, K=256 (NK=8), D[128m][128n] = sum_k A[m][k]*B[n][k].
// LM 0: compose  (A split, 3-term; out split g_Uw)
// LM 1: merged winograd (A=V SPLIT, 3-term) + vproj (A=fT plain, 2-term)
// LM 3: outproj (+resid, BN, SiLU) (A plain, 2-term)
// 256 threads = 8 warps (2m x 4n), warp tile 64x32, 3-buffer cp.async ring.
// ---------------------------------------------------------------------------
template<int LM>
__global__ __launch_bounds__(256, 2)
void mm_all(const float* __restrict__ resid, float* __restrict__ outp)
{
    extern __shared__ float sm[];

    const int b    = blockIdx.z;
    const int tid  = threadIdx.x;
    const int wid  = tid >> 5;
    const int lane = tid & 31;
    const int wm   = wid >> 2;
    const int wn   = wid & 3;
    const int gid  = lane >> 2;
    const int tig  = lane & 3;
    const int l8   = lane & 7;
    const int lm   = (lane >> 3) & 1;
    const int lh   = lane >> 4;

    // ---- per-CTA mode & geometry ----
    int mode, m0, n0, lvl = 0, M_act = 1 << 30;
    long mBase = 0;
    const __half *Abase, *Bbase;
    if (LM == 1) {
        int idx = blockIdx.x;
        if (idx < 384) {
            mode = 1;
            int t = idx / 24, sub = idx % 24;
            m0 = (sub & 7) * 128; n0 = (sub >> 3) * 128;
            Abase = g_V + ((long)(t * 4 + b) * 1024) * WROW;
            Bbase = g_Uw + (long)t * 384 * WROW;
            mBase = ((long)(t * 4 + b) * 1024) * 384;
            M_act = 1024;
        } else {
            mode = 2; int tv = idx - 384;
            int nt = (tv >= 43) ? 1 : 0;
            int mtile = tv - nt * 43;
            while (mtile >= c_vts[lvl + 1]) lvl++;
            m0 = (mtile - c_vts[lvl]) * 128;
            n0 = nt * 128;
            M_act = c_mact[lvl];
            Abase = g_fT + (long)b * VPIX * AROW + (long)c_vpix[lvl] * AROW;
            Bbase = g_vw + lvl * 256 * WROW;
        }
    } else if (LM == 0) {
        mode = 0; m0 = blockIdx.x * 128; n0 = blockIdx.y * 128;
        Abase = g_W2; Bbase = g_qwT;
        M_act = 6144;
    } else {
        mode = 3; m0 = blockIdx.x * 128; n0 = blockIdx.y * 128;
        Abase = g_att + (long)b * HW * AROW; Bbase = g_ow;
        M_act = 4096;
    }
    const bool splitA = (LM == 0) || (LM == 1 && mode == 1);

    // ---- hoisted loader state ----
    const int r0    = tid >> 3;
    const int sub   = tid & 7;
    const int plane = sub >> 2;
    const int kc    = sub & 3;
    const int phys  = sub ^ (r0 & 7);
    const uint32_t smb = smem_u32(sm);

    const __half* aBW = Abase + (long)(m0 + r0) * WROW + plane * 256 + kc * 8;   // split
    const __half* aBA = Abase + (long)(m0 + r0) * AROW + sub * 8;                // plain (sub<4)
    const __half* bP  = Bbase + (long)(n0 + r0) * WROW + plane * 256 + kc * 8;
    const uint32_t dA0 = smb + r0 * 128 + phys * 16;
    const uint32_t dB0 = dA0 + 3 * STG_B;

    bool aOK[4];
#pragma unroll
    for (int i = 0; i < 4; i++) aOK[i] = (m0 + r0 + 32 * i) < M_act;

    float acc[4][4][4];
#pragma unroll
    for (int mt = 0; mt < 4; mt++)
#pragma unroll
        for (int nt = 0; nt < 4; nt++)
#pragma unroll
            for (int r = 0; r < 4; r++) acc[mt][nt][r] = 0.f;

    auto load_stage = [&](int s, int buf) {
        const __half* bp = bP + s * 32;
        const uint32_t dB = dB0 + buf * STG_B;
#pragma unroll
        for (int i = 0; i < 4; i++)
            cp16(dB + i * 4096, bp + i * 32 * WROW, true);
        const uint32_t dA = dA0 + buf * STG_B;
        if (splitA) {
            const __half* ap = aBW + s * 32;
#pragma unroll
            for (int i = 0; i < 4; i++)
                cp16(dA + i * 4096, aOK[i] ? (ap + i * 32 * WROW) : (const void*)Abase, aOK[i]);
        } else if (sub < 4) {
            const __half* ap = aBA + s * 32;
#pragma unroll
            for (int i = 0; i < 4; i++)
                cp16(dA + i * 4096, aOK[i] ? (ap + i * 32 * AROW) : (const void*)Abase, aOK[i]);
        }
    };

    load_stage(0, 0); cp_commit();
    load_stage(1, 1); cp_commit();

    for (int s = 0; s < 8; s++) {
        const int buf = s % 3;
        cp_wait1();
        __syncthreads();
        if (s + 2 < 8) { load_stage(s + 2, (s + 2) % 3); }
        cp_commit();

        const uint32_t aBase_s = smb + buf * STG_B;
        const uint32_t bBase_s = smb + (3 + buf) * STG_B;
#pragma unroll
        for (int kk = 0; kk < 2; kk++) {
            const int chH = kk * 2 + lh;
            const int chL = chH + 4;
            uint32_t ah[4][4], al[4][4], bh[4][2], bl[4][2];
#pragma unroll
            for (int mt = 0; mt < 4; mt++) {
                int row = wm * 64 + mt * 16 + l8 + lm * 8;
                uint32_t base = aBase_s + row * 128;
                LDSM_X4(ah[mt][0], ah[mt][1], ah[mt][2], ah[mt][3],
                        base + ((chH ^ l8) << 4));
                if (splitA)
                    LDSM_X4(al[mt][0], al[mt][1], al[mt][2], al[mt][3],
                            base + ((chL ^ l8) << 4));
            }
#pragma unroll
            for (int np = 0; np < 2; np++) {
                int row = wn * 32 + np * 16 + l8 + lm * 8;
                uint32_t base = bBase_s + row * 128;
                LDSM_X4(bh[2 * np][0], bh[2 * np + 1][0],
                        bh[2 * np][1], bh[2 * np + 1][1],
                        base + ((chH ^ l8) << 4));
                LDSM_X4(bl[2 * np][0], bl[2 * np + 1][0],
                        bl[2 * np][1], bl[2 * np + 1][1],
                        base + ((chL ^ l8) << 4));
            }
            if (splitA) {
#pragma unroll
                for (int mt = 0; mt < 4; mt++)
#pragma unroll
                    for (int nt = 0; nt < 4; nt++) {
                        mma_f16(acc[mt][nt], ah[mt], bh[nt]);
                        mma_f16(acc[mt][nt], ah[mt], bl[nt]);
                        mma_f16(acc[mt][nt], al[mt], bh[nt]);
                    }
            } else {
#pragma unroll
                for (int mt = 0; mt < 4; mt++)
#pragma unroll
                    for (int nt = 0; nt < 4; nt++) {
                        mma_f16(acc[mt][nt], ah[mt], bh[nt]);
                        mma_f16(acc[mt][nt], ah[mt], bl[nt]);
                    }
            }
        }
    }

    // ---- epilogues ----
#pragma unroll
    for (int mt = 0; mt < 4; mt++) {
        int r0e = m0 + wm * 64 + mt * 16 + gid;
#pragma unroll
        for (int nt = 0; nt < 4; nt++) {
            int col = n0 + wn * 32 + nt * 8 + tig * 2;
#pragma unroll
            for (int h = 0; h < 2; h++) {
                int r = r0e + h * 8;
                float vx = acc[mt][nt][2 * h];
                float vy = acc[mt][nt][2 * h + 1];
                if (mode == 0) {
                    long e = (long)r * WROW + col;
                    __half hh, ll;
                    split_h(vx, hh, ll); g_Uw[e]     = hh; g_Uw[e + 256]     = ll;
                    split_h(vy, hh, ll); g_Uw[e + 1] = hh; g_Uw[e + 1 + 256] = ll;
                } else if (mode == 1) {
                    *(float2*)&g_M[mBase + (long)r * 384 + col] = make_float2(vx, vy);
                } else if (mode == 2) {
                    if (r < M_act) {
                        long row = c_vpix[lvl] + r;
                        *(__half2*)&g_v[(long)b * VSTRF + row * 256 + col] =
                            __floats2half2_rn(vx, vy);
                    }
                } else {
                    const float* qb = resid + (long)b * 256 * HW;
                    float* yb = outp + (long)b * 256 * HW;
#pragma unroll
                    for (int j = 0; j < 2; j++) {
                        int oc = col + j;
                        float x  = ((j == 0) ? vx : vy) + qb[(long)oc * HW + r];
                        float xn = x * g_bns[oc] + g_bnb[oc];
                        yb[(long)oc * HW + r] = xn / (1.f + expf(-xn));
                    }
                }
            }
        }
    }
}

// ---------------------------------------------------------------------------
// Merged: feat transposes (x<170) + winograd input transform (x>=170).
// ---------------------------------------------------------------------------
__global__ __launch_bounds__(256)
void prepActs(const float* __restrict__ q,
              const float* __restrict__ f0, const float* __restrict__ f1,
              const float* __restrict__ f2, const float* __restrict__ f3)
{
    __shared__ float tbuf[32][33];
    __shared__ float s[4][18][32];
    const int b = blockIdx.z;
    const int tid = threadIdx.x;

    if (blockIdx.x < 170) {
        int lvl = 0;
        while ((int)blockIdx.x >= c_ftk[lvl + 1]) lvl++;
        const int P  = c_mact[lvl];
        const int p0 = (blockIdx.x - c_ftk[lvl]) * 32;
        const float* I = (lvl == 0 ? f0 : lvl == 1 ? f1 : lvl == 2 ? f2 : f3)
                       + (long)b * 256 * P;
        __half* Of = g_fT + (long)b * VPIX * AROW + (long)c_vpix[lvl] * AROW;
        const int c0 = blockIdx.y * 32;
        const int tx = tid & 31, ty = tid >> 5;
#pragma unroll
        for (int i = 0; i < 32; i += 8)
            tbuf[ty + i][tx] = I[(long)(c0 + ty + i) * P + p0 + tx];
        __syncthreads();
#pragma unroll
        for (int i = 0; i < 32; i += 8)
            Of[(long)(p0 + ty + i) * AROW + c0 + tx] = __float2half_rn(tbuf[tx][ty + i]);
    } else {
        const int e   = blockIdx.x - 170;   // 0..127
        const int txg = e & 3, tyr = e >> 2;
        const int cg  = blockIdx.y;         // 0..7
        for (int idx = tid; idx < 2304; idx += 256) {
            int cc  = idx / 72;
            int rem = idx - cc * 72;
            int row = rem / 18;
            int col = rem - row * 18;
            int gy = 2 * tyr - 1 + row;
            int gx = txg * 16 - 1 + col;
            float v = 0.f;
            if (gy >= 0 && gy < 64 && gx >= 0 && gx < 64)
                v = q[((long)b * 256 + cg * 32 + cc) * 4096 + gy * 64 + gx];
            s[row][col][cc] = v;
        }
        __syncthreads();
        const int lane = tid & 31, tx = tid >> 5;   // 8 warps = 8 tiles
        float d[4][4];
#pragma unroll
        for (int i = 0; i < 4; i++)
#pragma unroll
            for (int j = 0; j < 4; j++) d[i][j] = s[i][2 * tx + j][lane];
        float t1[4][4];
#pragma unroll
        for (int j = 0; j < 4; j++) {
            t1[0][j] = d[0][j] - d[2][j];
            t1[1][j] = d[1][j] + d[2][j];
            t1[2][j] = d[2][j] - d[1][j];
            t1[3][j] = d[1][j] - d[3][j];
        }
        float V[4][4];
#pragma unroll
        for (int i = 0; i < 4; i++) {
            V[i][0] = t1[i][0] - t1[i][2];
            V[i][1] = t1[i][1] + t1[i][2];
            V[i][2] = t1[i][2] - t1[i][1];
            V[i][3] = t1[i][1] - t1[i][3];
        }
        const int tile = tyr * 32 + txg * 8 + tx;
#pragma unroll
        for (int i = 0; i < 4; i++)
#pragma unroll
            for (int j = 0; j < 4; j++) {
                int t = i * 4 + j;
                __half h, l;
                split_h(V[i][j], h, l);
                long base = ((long)(t * 4 + b) * 1024 + tile) * WROW + cg * 32 + lane;
                g_V[base] = h; g_V[base + 256] = l;
            }
    }
}

// ---------------------------------------------------------------------------
// Weight prep (one launch).
// ---------------------------------------------------------------------------
#define S0 262144
#define S1 (S0 + 65536)
#define S2 (S1 + 65536)
#define S3 (S2 + 1572864)
#define S4 (S3 + 384)
#define S5 (S4 + 256)

__global__ void prep_all(const float* __restrict__ qw, const float* __restrict__ vw,
                         const float* __restrict__ ow,
                         const float* __restrict__ offw, const float* __restrict__ attw,
                         const float* __restrict__ offb, const float* __restrict__ attb,
                         const float* __restrict__ bg, const float* __restrict__ bb,
                         const float* __restrict__ bm, const float* __restrict__ bv)
{
    long i = (long)blockIdx.x * 256 + threadIdx.x;
    if (i < S0) {
        long l = i >> 16, rem = i & 65535;
        long o = rem >> 8, c = rem & 255;
        __half h, lo;
        split_h(vw[i], h, lo);
        long e = l * (256 * WROW) + o * WROW + c;
        g_vw[e] = h; g_vw[e + 256] = lo;
    } else if (i < S1) {
        long j = i - S0;
        long o = j >> 8, c = j & 255;
        __half h, lo;
        split_h(ow[j], h, lo);
        g_ow[o * WROW + c] = h; g_ow[o * WROW + c + 256] = lo;
    } else if (i < S2) {
        long j = i - S1;
        long c = j >> 8, m = j & 255;
        __half h, lo;
        split_h(qw[m * 256 + c], h, lo);
        g_qwT[c * WROW + m] = h; g_qwT[c * WROW + m + 256] = lo;
    } else if (i < S3) {
        long j = i - S2;
        int t = (int)(j / 98304);
        int rem = (int)(j - (long)t * 98304);
        int o = rem >> 8, m = rem & 255;
        int ti = t >> 2, tj = t & 3;
        const float* wsrc = (o < 256) ? offw + ((long)o * 256 + m) * 9
                                      : attw + ((long)(o - 256) * 256 + m) * 9;
        float acc = 0.f;
#pragma unroll
        for (int ki = 0; ki < 3; ki++)
#pragma unroll
            for (int kj = 0; kj < 3; kj++)
                acc += G4[ti][ki] * G4[tj][kj] * wsrc[ki * 3 + kj];
        __half h, lo;
        split_h(acc, h, lo);
        long e = ((long)t * 384 + o) * WROW + m;
        g_W2[e] = h; g_W2[e + 256] = lo;
    } else if (i < S4) {
        long j = i - S3;
        g_cb[j] = (j < 256) ? offb[j] : attb[j - 256];
    } else if (i < S5) {
        long j = i - S4;
        float sc = bg[j] * rsqrtf(bv[j] + BN_EPS);
        g_bns[j] = sc;
        g_bnb[j] = bb[j] - bm[j] * sc;
    }
}

// ---------------------------------------------------------------------------
// Fused winograd output transform + deformable sampling (v in fp16).
// ---------------------------------------------------------------------------
__global__ __launch_bounds__(384)
void wgSample()
{
    __shared__ float scv[4][384];
    const int tile = blockIdx.x;
    const int b    = blockIdx.y;
    const int tid  = threadIdx.x;

    // ---- phase 1: output transform ----
    {
        const int oc = tid;
        const long tstr = (long)4 * 1024 * 384;
        const long base = ((long)b * 1024 + tile) * 384 + oc;
        float m[4][4];
#pragma unroll
        for (int t = 0; t < 16; t++)
            m[t >> 2][t & 3] = g_M[(long)t * tstr + base];
        const float bs = g_cb[oc];
#pragma unroll
        for (int i = 0; i < 2; i++) {
            float t0 = (i == 0) ? (m[0][0] + m[1][0] + m[2][0]) : (m[1][0] - m[2][0] - m[3][0]);
            float t1 = (i == 0) ? (m[0][1] + m[1][1] + m[2][1]) : (m[1][1] - m[2][1] - m[3][1]);
            float t2 = (i == 0) ? (m[0][2] + m[1][2] + m[2][2]) : (m[1][2] - m[2][2] - m[3][2]);
            float t3 = (i == 0) ? (m[0][3] + m[1][3] + m[2][3]) : (m[1][3] - m[2][3] - m[3][3]);
            scv[i * 2 + 0][oc] = t0 + t1 + t2 + bs;
            scv[i * 2 + 1][oc] = t1 - t2 - t3 + bs;
        }
    }
    __syncthreads();

    // ---- phase 2: sampling ----
    const int warp = tid >> 5;
    const int lane = tid & 31;
    const int ty = tile >> 5, tx = tile & 31;

    for (int p = warp; p < 32; p += 12) {
        const int pxl = p >> 3;
        const int h   = p & 7;
        const int py  = 2 * ty + (pxl >> 1);
        const int px  = 2 * tx + (pxl & 1);
        const int pix = py * 64 + px;
        const float refx = -1.f + 2.f * (float)px / 63.f;
        const float refy = -1.f + 2.f * (float)py / 63.f;

        float lg = -INFINITY, ox = 0.f, oy = 0.f;
        if (lane < 16) {
            lg = scv[pxl][256 + h * 16 + lane];
            ox = tanhf(scv[pxl][h * 32 + 2 * lane    ]) * 0.25f;
            oy = tanhf(scv[pxl][h * 32 + 2 * lane + 1]) * 0.25f;
        }
        float mx = lg;
#pragma unroll
        for (int s = 16; s > 0; s >>= 1)
            mx = fmaxf(mx, __shfl_xor_sync(0xFFFFFFFFu, mx, s));
        float e = (lane < 16) ? expf(lg - mx) : 0.f;
        float sum = e;
#pragma unroll
        for (int s = 16; s > 0; s >>= 1)
            sum += __shfl_xor_sync(0xFFFFFFFFu, sum, s);
        float wgt = e / sum;

        const __half* vb = g_v + (long)b * VSTRF + h * 32 + lane;
        float acc = 0.f;
#pragma unroll
        for (int i = 0; i < 16; i++) {
            const int lvl = i >> 2;
            const int sz  = 64 >> lvl;
            float aw = __shfl_sync(0xFFFFFFFFu, wgt, i);
            float gx = refx + __shfl_sync(0xFFFFFFFFu, ox, i);
            float gy = refy + __shfl_sync(0xFFFFFFFFu, oy, i);

            float xf = (gx + 1.f) * 0.5f * (float)(sz - 1);
            float yf = (gy + 1.f) * 0.5f * (float)(sz - 1);
            float x0f = floorf(xf), y0f = floorf(yf);
            int x0 = (int)x0f, y0 = (int)y0f;
            int x1 = x0 + 1,  y1 = y0 + 1;
            float wx1 = xf - x0f, wx0 = 1.f - wx1;
            float wy1 = yf - y0f, wy0 = 1.f - wy1;

            const __half* vl = vb + c_voff[lvl];
            if (x0 >= 0 && x0 < sz && y0 >= 0 && y0 < sz)
                acc = fmaf(aw * wx0 * wy0, __half2float(vl[(y0 * sz + x0) * 256]), acc);
            if (x1 >= 0 && x1 < sz && y0 >= 0 && y0 < sz)
                acc = fmaf(aw * wx1 * wy0, __half2float(vl[(y0 * sz + x1) * 256]), acc);
            if (x0 >= 0 && x0 < sz && y1 >= 0 && y1 < sz)
                acc = fmaf(aw * wx0 * wy1, __half2float(vl[(y1 * sz + x0) * 256]), acc);
            if (x1 >= 0 && x1 < sz && y1 >= 0 && y1 < sz)
                acc = fmaf(aw * wx1 * wy1, __half2float(vl[(y1 * sz + x1) * 256]), acc);
        }

        g_att[((long)b * HW + pix) * AROW + h * 32 + lane] = __float2half_rn(acc);
    }
}

// ---------------------------------------------------------------------------
// Launch. Main GEMM is the 4th launch (ncu capture slot).
// ---------------------------------------------------------------------------
extern "C" void kernel_launch(void* const* d_in, const int* in_sizes, int n_in,
                              void* d_out, int out_size)
{
    const float* query  = (const float*)d_in[0];
    const float* feat0  = (const float*)d_in[1];
    const float* feat1  = (const float*)d_in[2];
    const float* feat2  = (const float*)d_in[3];
    const float* feat3  = (const float*)d_in[4];
    const float* q_w    = (const float*)d_in[5];
    const float* v_w    = (const float*)d_in[6];
    const float* out_w  = (const float*)d_in[7];
    const float* off_w  = (const float*)d_in[8];
    const float* off_b  = (const float*)d_in[9];
    const float* attn_w = (const float*)d_in[10];
    const float* attn_b = (const float*)d_in[11];
    const float* bn_g   = (const float*)d_in[12];
    const float* bn_b   = (const float*)d_in[13];
    const float* bn_m   = (const float*)d_in[14];
    const float* bn_v   = (const float*)d_in[15];
    float* out = (float*)d_out;

    cudaFuncSetAttribute(mm_all<0>, cudaFuncAttributeMaxDynamicSharedMemorySize, DSMEM_SZ);
    cudaFuncSetAttribute(mm_all<1>, cudaFuncAttributeMaxDynamicSharedMemorySize, DSMEM_SZ);
    cudaFuncSetAttribute(mm_all<3>, cudaFuncAttributeMaxDynamicSharedMemorySize, DSMEM_SZ);

    // 1. weight prep
    prep_all<<<(S5 + 255) / 256, 256>>>(q_w, v_w, out_w, off_w, attn_w,
                                        off_b, attn_b, bn_g, bn_b, bn_m, bn_v);
    // 2. feat transposes + winograd input transform (split V)
    prepActs<<<dim3(298, 8, BATCH), 256>>>(query, feat0, feat1, feat2, feat3);

    // 3. compose winograd weights (3-term)
    mm_all<0><<<dim3(48, 2, 1), 256, DSMEM_SZ>>>(nullptr, nullptr);

    // 4. merged winograd (3-term) + vproj (2-term) GEMM  <-- ncu capture slot
    mm_all<1><<<dim3(470, 1, BATCH), 256, DSMEM_SZ>>>(nullptr, nullptr);

    // 5. fused winograd output transform + sampling (fp16 v)
    wgSample<<<dim3(1024, BATCH), 384>>>();

    // 6. output projection + residual + BN + SiLU
    mm_all<3><<<dim3(32, 2, BATCH), 256, DSMEM_SZ>>>(query, out);
}

// round 14
// speedup vs baseline: 1.0646x; 1.0646x over previous
#include <cuda_runtime.h>
#include <cuda_fp16.h>
#include <math.h>
#include <stdint.h>

// ---------------------------------------------------------------------------
// Problem constants
// ---------------------------------------------------------------------------
#define BATCH   4
#define HW      4096
#define BN_EPS  1e-5f
#define VPIX    5440
#define VSTRF   (VPIX*256)
#define WROW    512                  // split row: [256 hi][256 lo] fp16
#define AROW    256                  // plain activation row: 256 fp16
#define NT      36                   // winograd F(4,3): 6x6 transform points
#define NTILE   256                  // 16x16 tiles of 4x4 output per image

__device__ __constant__ int c_voff[4] = {0, 1048576, 1310720, 1376256};
__device__ __constant__ int c_vpix[4] = {0, 4096, 5120, 5376};
__device__ __constant__ int c_mact[4] = {4096, 1024, 256, 64};
__device__ __constant__ int c_vts[5]  = {0, 32, 40, 42, 43};
__device__ __constant__ int c_ftk[5]  = {0, 128, 160, 168, 170};
__constant__ float G6[6][3] = {
    {0.25f, 0.f, 0.f},
    {-1.f/6.f, -1.f/6.f, -1.f/6.f},
    {-1.f/6.f,  1.f/6.f, -1.f/6.f},
    {1.f/24.f,  1.f/12.f, 1.f/6.f},
    {1.f/24.f, -1.f/12.f, 1.f/6.f},
    {0.f, 0.f, 1.f}};

// ---------------------------------------------------------------------------
// Scratch
// ---------------------------------------------------------------------------
__device__ __half g_fT [BATCH * VPIX * AROW];      // feats fp16
__device__ __half g_att[BATCH * HW * AROW];        // sampler out fp16
__device__ __half g_qwT[256 * WROW];               // q_w^T split
__device__ __half g_vw [4 * 256 * WROW];           // v_w split
__device__ __half g_ow [256 * WROW];               // out_w split
__device__ __half g_W2 [NT * 384 * WROW];          // G-transformed conv w split
__device__ __half g_Uw [NT * 384 * WROW];          // winograd weights split
__device__ __half g_V  [(long)NT * 4 * NTILE * WROW]; // winograd input transform split
__device__ float g_M  [(long)NT * 4 * NTILE * 384];   // winograd GEMM out fp32
__device__ __half g_v  [BATCH * VSTRF];            // values fp16 channel-last
__device__ float g_cb [384];
__device__ float g_bns[256], g_bnb[256];

// ---------------------------------------------------------------------------
// Helpers
// ---------------------------------------------------------------------------
__device__ __forceinline__ uint32_t smem_u32(const void* p) {
    uint32_t a;
    asm("{ .reg .u64 t; cvta.to.shared.u64 t, %1; cvt.u32.u64 %0, t; }"
        : "=r"(a) : "l"(p));
    return a;
}
__device__ __forceinline__ void cp16(uint32_t dst, const void* src, bool v) {
    int sz = v ? 16 : 0;
    asm volatile("cp.async.cg.shared.global [%0], [%1], 16, %2;\n"
                 :: "r"(dst), "l"(src), "r"(sz) : "memory");
}
__device__ __forceinline__ void cp_commit() {
    asm volatile("cp.async.commit_group;\n" ::: "memory");
}
__device__ __forceinline__ void cp_wait1() {
    asm volatile("cp.async.wait_group 1;\n" ::: "memory");
}
__device__ __forceinline__ void mma_f16(float* c, const uint32_t* a, const uint32_t* b) {
    asm volatile(
        "mma.sync.aligned.m16n8k16.row.col.f32.f16.f16.f32 "
        "{%0,%1,%2,%3}, {%4,%5,%6,%7}, {%8,%9}, {%0,%1,%2,%3};"
        : "+f"(c[0]), "+f"(c[1]), "+f"(c[2]), "+f"(c[3])
        : "r"(a[0]), "r"(a[1]), "r"(a[2]), "r"(a[3]), "r"(b[0]), "r"(b[1]));
}
#define LDSM_X4(r0, r1, r2, r3, addr) \
    asm volatile("ldmatrix.sync.aligned.m8n8.x4.shared.b16 {%0,%1,%2,%3}, [%4];" \
        : "=r"(r0), "=r"(r1), "=r"(r2), "=r"(r3) : "r"(addr))

__device__ __forceinline__ void split_h(float x, __half& h, __half& l) {
    h = __float2half_rn(x);
    l = __float2half_rn(x - __half2float(h));
}

#define STG_B    16384
#define DSMEM_SZ (6 * STG_B)          // 96 KB -> 2 CTAs/SM

// ---------------------------------------------------------------------------
// Unified fp16 GEMM, K=256 (NK=8), D[128m][128n] = sum_k A[m][k]*B[n][k].
// LM 0: compose  (A split 3-term; rows 36*384)
// LM 1: merged winograd (A=V split, 3-term) + vproj (A=fT plain, 2-term)
// LM 3: outproj (+resid, BN, SiLU) (A plain, 2-term)
// ---------------------------------------------------------------------------
template<int LM>
__global__ __launch_bounds__(256, 2)
void mm_all(const float* __restrict__ resid, float* __restrict__ outp)
{
    extern __shared__ float sm[];

    const int b    = blockIdx.z;
    const int tid  = threadIdx.x;
    const int wid  = tid >> 5;
    const int lane = tid & 31;
    const int wm   = wid >> 2;
    const int wn   = wid & 3;
    const int gid  = lane >> 2;
    const int tig  = lane & 3;
    const int l8   = lane & 7;
    const int lm   = (lane >> 3) & 1;
    const int lh   = lane >> 4;

    // ---- per-CTA mode & geometry ----
    int mode, m0, n0, lvl = 0, M_act = 1 << 30;
    long mBase = 0;
    const __half *Abase, *Bbase;
    if (LM == 1) {
        int idx = blockIdx.x;
        if (idx < NT * 6) {          // 36 t * (2 m-tiles x 3 n-tiles)
            mode = 1;
            int t = idx / 6, sub = idx % 6;
            m0 = (sub & 1) * 128; n0 = (sub >> 1) * 128;
            Abase = g_V + ((long)(t * 4 + b) * NTILE) * WROW;
            Bbase = g_Uw + (long)t * 384 * WROW;
            mBase = ((long)(t * 4 + b) * NTILE) * 384;
            M_act = NTILE;
        } else {
            mode = 2; int tv = idx - NT * 6;
            int nt = (tv >= 43) ? 1 : 0;
            int mtile = tv - nt * 43;
            while (mtile >= c_vts[lvl + 1]) lvl++;
            m0 = (mtile - c_vts[lvl]) * 128;
            n0 = nt * 128;
            M_act = c_mact[lvl];
            Abase = g_fT + (long)b * VPIX * AROW + (long)c_vpix[lvl] * AROW;
            Bbase = g_vw + lvl * 256 * WROW;
        }
    } else if (LM == 0) {
        mode = 0; m0 = blockIdx.x * 128; n0 = blockIdx.y * 128;
        Abase = g_W2; Bbase = g_qwT;
        M_act = NT * 384;            // 13824 = 108*128 exact
    } else {
        mode = 3; m0 = blockIdx.x * 128; n0 = blockIdx.y * 128;
        Abase = g_att + (long)b * HW * AROW; Bbase = g_ow;
        M_act = 4096;
    }
    const bool splitA = (LM == 0) || (LM == 1 && mode == 1);

    // ---- hoisted loader state ----
    const int r0    = tid >> 3;
    const int sub   = tid & 7;
    const int plane = sub >> 2;
    const int kc    = sub & 3;
    const int phys  = sub ^ (r0 & 7);
    const uint32_t smb = smem_u32(sm);

    const __half* aBW = Abase + (long)(m0 + r0) * WROW + plane * 256 + kc * 8;
    const __half* aBA = Abase + (long)(m0 + r0) * AROW + sub * 8;
    const __half* bP  = Bbase + (long)(n0 + r0) * WROW + plane * 256 + kc * 8;
    const uint32_t dA0 = smb + r0 * 128 + phys * 16;
    const uint32_t dB0 = dA0 + 3 * STG_B;

    bool aOK[4];
#pragma unroll
    for (int i = 0; i < 4; i++) aOK[i] = (m0 + r0 + 32 * i) < M_act;

    float acc[4][4][4];
#pragma unroll
    for (int mt = 0; mt < 4; mt++)
#pragma unroll
        for (int nt = 0; nt < 4; nt++)
#pragma unroll
            for (int r = 0; r < 4; r++) acc[mt][nt][r] = 0.f;

    auto load_stage = [&](int s, int buf) {
        const __half* bp = bP + s * 32;
        const uint32_t dB = dB0 + buf * STG_B;
#pragma unroll
        for (int i = 0; i < 4; i++)
            cp16(dB + i * 4096, bp + i * 32 * WROW, true);
        const uint32_t dA = dA0 + buf * STG_B;
        if (splitA) {
            const __half* ap = aBW + s * 32;
#pragma unroll
            for (int i = 0; i < 4; i++)
                cp16(dA + i * 4096, aOK[i] ? (ap + i * 32 * WROW) : (const void*)Abase, aOK[i]);
        } else if (sub < 4) {
            const __half* ap = aBA + s * 32;
#pragma unroll
            for (int i = 0; i < 4; i++)
                cp16(dA + i * 4096, aOK[i] ? (ap + i * 32 * AROW) : (const void*)Abase, aOK[i]);
        }
    };

    load_stage(0, 0); cp_commit();
    load_stage(1, 1); cp_commit();

    for (int s = 0; s < 8; s++) {
        const int buf = s % 3;
        cp_wait1();
        __syncthreads();
        if (s + 2 < 8) { load_stage(s + 2, (s + 2) % 3); }
        cp_commit();

        const uint32_t aBase_s = smb + buf * STG_B;
        const uint32_t bBase_s = smb + (3 + buf) * STG_B;
#pragma unroll
        for (int kk = 0; kk < 2; kk++) {
            const int chH = kk * 2 + lh;
            const int chL = chH + 4;
            uint32_t ah[4][4], al[4][4], bh[4][2], bl[4][2];
#pragma unroll
            for (int mt = 0; mt < 4; mt++) {
                int row = wm * 64 + mt * 16 + l8 + lm * 8;
                uint32_t base = aBase_s + row * 128;
                LDSM_X4(ah[mt][0], ah[mt][1], ah[mt][2], ah[mt][3],
                        base + ((chH ^ l8) << 4));
                if (splitA)
                    LDSM_X4(al[mt][0], al[mt][1], al[mt][2], al[mt][3],
                            base + ((chL ^ l8) << 4));
            }
#pragma unroll
            for (int np = 0; np < 2; np++) {
                int row = wn * 32 + np * 16 + l8 + lm * 8;
                uint32_t base = bBase_s + row * 128;
                LDSM_X4(bh[2 * np][0], bh[2 * np + 1][0],
                        bh[2 * np][1], bh[2 * np + 1][1],
                        base + ((chH ^ l8) << 4));
                LDSM_X4(bl[2 * np][0], bl[2 * np + 1][0],
                        bl[2 * np][1], bl[2 * np + 1][1],
                        base + ((chL ^ l8) << 4));
            }
            if (splitA) {
#pragma unroll
                for (int mt = 0; mt < 4; mt++)
#pragma unroll
                    for (int nt = 0; nt < 4; nt++) {
                        mma_f16(acc[mt][nt], ah[mt], bh[nt]);
                        mma_f16(acc[mt][nt], ah[mt], bl[nt]);
                        mma_f16(acc[mt][nt], al[mt], bh[nt]);
                    }
            } else {
#pragma unroll
                for (int mt = 0; mt < 4; mt++)
#pragma unroll
                    for (int nt = 0; nt < 4; nt++) {
                        mma_f16(acc[mt][nt], ah[mt], bh[nt]);
                        mma_f16(acc[mt][nt], ah[mt], bl[nt]);
                    }
            }
        }
    }

    // ---- epilogues ----
#pragma unroll
    for (int mt = 0; mt < 4; mt++) {
        int r0e = m0 + wm * 64 + mt * 16 + gid;
#pragma unroll
        for (int nt = 0; nt < 4; nt++) {
            int col = n0 + wn * 32 + nt * 8 + tig * 2;
#pragma unroll
            for (int h = 0; h < 2; h++) {
                int r = r0e + h * 8;
                float vx = acc[mt][nt][2 * h];
                float vy = acc[mt][nt][2 * h + 1];
                if (mode == 0) {
                    long e = (long)r * WROW + col;
                    __half hh, ll;
                    split_h(vx, hh, ll); g_Uw[e]     = hh; g_Uw[e + 256]     = ll;
                    split_h(vy, hh, ll); g_Uw[e + 1] = hh; g_Uw[e + 1 + 256] = ll;
                } else if (mode == 1) {
                    if (r < M_act)
                        *(float2*)&g_M[mBase + (long)r * 384 + col] = make_float2(vx, vy);
                } else if (mode == 2) {
                    if (r < M_act) {
                        long row = c_vpix[lvl] + r;
                        *(__half2*)&g_v[(long)b * VSTRF + row * 256 + col] =
                            __floats2half2_rn(vx, vy);
                    }
                } else {
                    const float* qb = resid + (long)b * 256 * HW;
                    float* yb = outp + (long)b * 256 * HW;
#pragma unroll
                    for (int j = 0; j < 2; j++) {
                        int oc = col + j;
                        float x  = ((j == 0) ? vx : vy) + qb[(long)oc * HW + r];
                        float xn = x * g_bns[oc] + g_bnb[oc];
                        yb[(long)oc * HW + r] = xn / (1.f + expf(-xn));
                    }
                }
            }
        }
    }
}

// ---------------------------------------------------------------------------
// Merged: feat transposes (x<170) + F(4,3) winograd input transform (x>=170).
// Wino branch: 32 blocks (8 tiles each, 1 warp/tile), y = 8 channel groups.
// ---------------------------------------------------------------------------
__global__ __launch_bounds__(256)
void prepActs(const float* __restrict__ q,
              const float* __restrict__ f0, const float* __restrict__ f1,
              const float* __restrict__ f2, const float* __restrict__ f3)
{
    __shared__ float tbuf[32][33];
    __shared__ float s[6][34][32];
    const int b = blockIdx.z;
    const int tid = threadIdx.x;

    if (blockIdx.x < 170) {
        int lvl = 0;
        while ((int)blockIdx.x >= c_ftk[lvl + 1]) lvl++;
        const int P  = c_mact[lvl];
        const int p0 = (blockIdx.x - c_ftk[lvl]) * 32;
        const float* I = (lvl == 0 ? f0 : lvl == 1 ? f1 : lvl == 2 ? f2 : f3)
                       + (long)b * 256 * P;
        __half* Of = g_fT + (long)b * VPIX * AROW + (long)c_vpix[lvl] * AROW;
        const int c0 = blockIdx.y * 32;
        const int tx = tid & 31, ty = tid >> 5;
#pragma unroll
        for (int i = 0; i < 32; i += 8)
            tbuf[ty + i][tx] = I[(long)(c0 + ty + i) * P + p0 + tx];
        __syncthreads();
#pragma unroll
        for (int i = 0; i < 32; i += 8)
            Of[(long)(p0 + ty + i) * AROW + c0 + tx] = __float2half_rn(tbuf[tx][ty + i]);
    } else {
        const int e   = blockIdx.x - 170;   // 0..31
        const int ty  = e >> 1;             // tile row 0..15
        const int txg = (e & 1) * 8;        // first tile col of this block
        const int cg  = blockIdx.y;         // 0..7
        // load 6 x 34 x 32 patch (rows 4*ty-1.., cols 4*txg-1..)
        for (int idx = tid; idx < 6 * 34 * 32; idx += 256) {
            int cc  = idx / 204;
            int rem = idx - cc * 204;
            int row = rem / 34;
            int col = rem - row * 34;
            int gy = 4 * ty - 1 + row;
            int gx = 4 * txg - 1 + col;
            float v = 0.f;
            if (gy >= 0 && gy < 64 && gx >= 0 && gx < 64)
                v = q[((long)b * 256 + cg * 32 + cc) * 4096 + gy * 64 + gx];
            s[row][col][cc] = v;
        }
        __syncthreads();
        const int lane = tid & 31, w = tid >> 5;   // 8 warps = 8 tiles
        float d[6][6];
#pragma unroll
        for (int i = 0; i < 6; i++)
#pragma unroll
            for (int j = 0; j < 6; j++) d[i][j] = s[i][4 * w + j][lane];
        // t1 = B^T d
        float t1[6][6];
#pragma unroll
        for (int j = 0; j < 6; j++) {
            t1[0][j] = 4.f * d[0][j] - 5.f * d[2][j] + d[4][j];
            t1[1][j] = -4.f * d[1][j] - 4.f * d[2][j] + d[3][j] + d[4][j];
            t1[2][j] =  4.f * d[1][j] - 4.f * d[2][j] - d[3][j] + d[4][j];
            t1[3][j] = -2.f * d[1][j] - d[2][j] + 2.f * d[3][j] + d[4][j];
            t1[4][j] =  2.f * d[1][j] - d[2][j] - 2.f * d[3][j] + d[4][j];
            t1[5][j] =  4.f * d[1][j] - 5.f * d[3][j] + d[5][j];
        }
        // V = t1 B
        float V[6][6];
#pragma unroll
        for (int i = 0; i < 6; i++) {
            V[i][0] = 4.f * t1[i][0] - 5.f * t1[i][2] + t1[i][4];
            V[i][1] = -4.f * t1[i][1] - 4.f * t1[i][2] + t1[i][3] + t1[i][4];
            V[i][2] =  4.f * t1[i][1] - 4.f * t1[i][2] - t1[i][3] + t1[i][4];
            V[i][3] = -2.f * t1[i][1] - t1[i][2] + 2.f * t1[i][3] + t1[i][4];
            V[i][4] =  2.f * t1[i][1] - t1[i][2] - 2.f * t1[i][3] + t1[i][4];
            V[i][5] =  4.f * t1[i][1] - 5.f * t1[i][3] + t1[i][5];
        }
        const int tile = ty * 16 + txg + w;
#pragma unroll
        for (int i = 0; i < 6; i++)
#pragma unroll
            for (int j = 0; j < 6; j++) {
                int t = i * 6 + j;
                __half h, l;
                split_h(V[i][j], h, l);
                long base = ((long)(t * 4 + b) * NTILE + tile) * WROW + cg * 32 + lane;
                g_V[base] = h; g_V[base + 256] = l;
            }
    }
}

// ---------------------------------------------------------------------------
// Weight prep (one launch).
// ---------------------------------------------------------------------------
#define S0 262144
#define S1 (S0 + 65536)
#define S2 (S1 + 65536)
#define S3 (S2 + NT * 98304)
#define S4 (S3 + 384)
#define S5 (S4 + 256)

__global__ void prep_all(const float* __restrict__ qw, const float* __restrict__ vw,
                         const float* __restrict__ ow,
                         const float* __restrict__ offw, const float* __restrict__ attw,
                         const float* __restrict__ offb, const float* __restrict__ attb,
                         const float* __restrict__ bg, const float* __restrict__ bb,
                         const float* __restrict__ bm, const float* __restrict__ bv)
{
    long i = (long)blockIdx.x * 256 + threadIdx.x;
    if (i < S0) {
        long l = i >> 16, rem = i & 65535;
        long o = rem >> 8, c = rem & 255;
        __half h, lo;
        split_h(vw[i], h, lo);
        long e = l * (256 * WROW) + o * WROW + c;
        g_vw[e] = h; g_vw[e + 256] = lo;
    } else if (i < S1) {
        long j = i - S0;
        long o = j >> 8, c = j & 255;
        __half h, lo;
        split_h(ow[j], h, lo);
        g_ow[o * WROW + c] = h; g_ow[o * WROW + c + 256] = lo;
    } else if (i < S2) {
        long j = i - S1;
        long c = j >> 8, m = j & 255;
        __half h, lo;
        split_h(qw[m * 256 + c], h, lo);
        g_qwT[c * WROW + m] = h; g_qwT[c * WROW + m + 256] = lo;
    } else if (i < S3) {
        long j = i - S2;
        int t = (int)(j / 98304);
        int rem = (int)(j - (long)t * 98304);
        int o = rem >> 8, m = rem & 255;
        int ti = t / 6, tj = t % 6;
        const float* wsrc = (o < 256) ? offw + ((long)o * 256 + m) * 9
                                      : attw + ((long)(o - 256) * 256 + m) * 9;
        float acc = 0.f;
#pragma unroll
        for (int ki = 0; ki < 3; ki++)
#pragma unroll
            for (int kj = 0; kj < 3; kj++)
                acc += G6[ti][ki] * G6[tj][kj] * wsrc[ki * 3 + kj];
        __half h, lo;
        split_h(acc, h, lo);
        long e = ((long)t * 384 + o) * WROW + m;
        g_W2[e] = h; g_W2[e + 256] = lo;
    } else if (i < S4) {
        long j = i - S3;
        g_cb[j] = (j < 256) ? offb[j] : attb[j - 256];
    } else if (i < S5) {
        long j = i - S4;
        float sc = bg[j] * rsqrtf(bv[j] + BN_EPS);
        g_bns[j] = sc;
        g_bnb[j] = bb[j] - bm[j] * sc;
    }
}

// ---------------------------------------------------------------------------
// Fused F(4,3) winograd output transform + deformable sampling.
// Block = one 4x4 tile: 512 threads.
//   Phase 1 (tid<384): thread oc: Y = A^T M A + bias -> smem scv[16][384]
//   Phase 2: 16 warps x 8 tasks (pixel = warp, head = task).
// ---------------------------------------------------------------------------
__global__ __launch_bounds__(512)
void wgSample()
{
    __shared__ float scv[16][384];
    const int tile = blockIdx.x;
    const int b    = blockIdx.y;
    const int tid  = threadIdx.x;

    if (tid < 384) {
        const int oc = tid;
        const long tstr = (long)4 * NTILE * 384;
        const long base = ((long)b * NTILE + tile) * 384 + oc;
        float m[6][6];
#pragma unroll
        for (int t = 0; t < NT; t++)
            m[t / 6][t % 6] = g_M[(long)t * tstr + base];
        // tmp = A^T m  (4x6)
        float tp[4][6];
#pragma unroll
        for (int j = 0; j < 6; j++) {
            tp[0][j] = m[0][j] + m[1][j] + m[2][j] + m[3][j] + m[4][j];
            tp[1][j] = m[1][j] - m[2][j] + 2.f * m[3][j] - 2.f * m[4][j];
            tp[2][j] = m[1][j] + m[2][j] + 4.f * m[3][j] + 4.f * m[4][j];
            tp[3][j] = m[1][j] - m[2][j] + 8.f * m[3][j] - 8.f * m[4][j] + m[5][j];
        }
        const float bs = g_cb[oc];
#pragma unroll
        for (int r = 0; r < 4; r++) {
            float y0 = tp[r][0] + tp[r][1] + tp[r][2] + tp[r][3] + tp[r][4];
            float y1 = tp[r][1] - tp[r][2] + 2.f * tp[r][3] - 2.f * tp[r][4];
            float y2 = tp[r][1] + tp[r][2] + 4.f * tp[r][3] + 4.f * tp[r][4];
            float y3 = tp[r][1] - tp[r][2] + 8.f * tp[r][3] - 8.f * tp[r][4] + tp[r][5];
            scv[r * 4 + 0][oc] = y0 + bs;
            scv[r * 4 + 1][oc] = y1 + bs;
            scv[r * 4 + 2][oc] = y2 + bs;
            scv[r * 4 + 3][oc] = y3 + bs;
        }
    }
    __syncthreads();

    // ---- phase 2: sampling. warp = pixel (0..15), 8 heads per warp ----
    const int warp = tid >> 5;
    const int lane = tid & 31;
    const int ty = tile >> 4, tx = tile & 15;
    const int pxl = warp;
    const int py  = 4 * ty + (pxl >> 2);
    const int px  = 4 * tx + (pxl & 3);
    const int pix = py * 64 + px;
    const float refx = -1.f + 2.f * (float)px / 63.f;
    const float refy = -1.f + 2.f * (float)py / 63.f;

    for (int h = 0; h < 8; h++) {
        float lg = -INFINITY, ox = 0.f, oy = 0.f;
        if (lane < 16) {
            lg = scv[pxl][256 + h * 16 + lane];
            ox = tanhf(scv[pxl][h * 32 + 2 * lane    ]) * 0.25f;
            oy = tanhf(scv[pxl][h * 32 + 2 * lane + 1]) * 0.25f;
        }
        float mx = lg;
#pragma unroll
        for (int s = 16; s > 0; s >>= 1)
            mx = fmaxf(mx, __shfl_xor_sync(0xFFFFFFFFu, mx, s));
        float e = (lane < 16) ? expf(lg - mx) : 0.f;
        float sum = e;
#pragma unroll
        for (int s = 16; s > 0; s >>= 1)
            sum += __shfl_xor_sync(0xFFFFFFFFu, sum, s);
        float wgt = e / sum;

        const __half* vb = g_v + (long)b * VSTRF + h * 32 + lane;
        float acc = 0.f;
#pragma unroll
        for (int i = 0; i < 16; i++) {
            const int lvl = i >> 2;
            const int sz  = 64 >> lvl;
            float aw = __shfl_sync(0xFFFFFFFFu, wgt, i);
            float gx = refx + __shfl_sync(0xFFFFFFFFu, ox, i);
            float gy = refy + __shfl_sync(0xFFFFFFFFu, oy, i);

            float xf = (gx + 1.f) * 0.5f * (float)(sz - 1);
            float yf = (gy + 1.f) * 0.5f * (float)(sz - 1);
            float x0f = floorf(xf), y0f = floorf(yf);
            int x0 = (int)x0f, y0 = (int)y0f;
            int x1 = x0 + 1,  y1 = y0 + 1;
            float wx1 = xf - x0f, wx0 = 1.f - wx1;
            float wy1 = yf - y0f, wy0 = 1.f - wy1;

            const __half* vl = vb + c_voff[lvl];
            if (x0 >= 0 && x0 < sz && y0 >= 0 && y0 < sz)
                acc = fmaf(aw * wx0 * wy0, __half2float(vl[(y0 * sz + x0) * 256]), acc);
            if (x1 >= 0 && x1 < sz && y0 >= 0 && y0 < sz)
                acc = fmaf(aw * wx1 * wy0, __half2float(vl[(y0 * sz + x1) * 256]), acc);
            if (x0 >= 0 && x0 < sz && y1 >= 0 && y1 < sz)
                acc = fmaf(aw * wx0 * wy1, __half2float(vl[(y1 * sz + x0) * 256]), acc);
            if (x1 >= 0 && x1 < sz && y1 >= 0 && y1 < sz)
                acc = fmaf(aw * wx1 * wy1, __half2float(vl[(y1 * sz + x1) * 256]), acc);
        }

        g_att[((long)b * HW + pix) * AROW + h * 32 + lane] = __float2half_rn(acc);
    }
}

// ---------------------------------------------------------------------------
// Launch. Main GEMM is the 4th launch (ncu capture slot).
// ---------------------------------------------------------------------------
extern "C" void kernel_launch(void* const* d_in, const int* in_sizes, int n_in,
                              void* d_out, int out_size)
{
    const float* query  = (const float*)d_in[0];
    const float* feat0  = (const float*)d_in[1];
    const float* feat1  = (const float*)d_in[2];
    const float* feat2  = (const float*)d_in[3];
    const float* feat3  = (const float*)d_in[4];
    const float* q_w    = (const float*)d_in[5];
    const float* v_w    = (const float*)d_in[6];
    const float* out_w  = (const float*)d_in[7];
    const float* off_w  = (const float*)d_in[8];
    const float* off_b  = (const float*)d_in[9];
    const float* attn_w = (const float*)d_in[10];
    const float* attn_b = (const float*)d_in[11];
    const float* bn_g   = (const float*)d_in[12];
    const float* bn_b   = (const float*)d_in[13];
    const float* bn_m   = (const float*)d_in[14];
    const float* bn_v   = (const float*)d_in[15];
    float* out = (float*)d_out;

    cudaFuncSetAttribute(mm_all<0>, cudaFuncAttributeMaxDynamicSharedMemorySize, DSMEM_SZ);
    cudaFuncSetAttribute(mm_all<1>, cudaFuncAttributeMaxDynamicSharedMemorySize, DSMEM_SZ);
    cudaFuncSetAttribute(mm_all<3>, cudaFuncAttributeMaxDynamicSharedMemorySize, DSMEM_SZ);

    // 1. weight prep (incl. F(4,3) G-transform)
    prep_all<<<(S5 + 255) / 256, 256>>>(q_w, v_w, out_w, off_w, attn_w,
                                        off_b, attn_b, bn_g, bn_b, bn_m, bn_v);
    // 2. feat transposes + F(4,3) input transform (split V)
    prepActs<<<dim3(202, 8, BATCH), 256>>>(query, feat0, feat1, feat2, feat3);

    // 3. compose winograd weights (3-term): rows 36*384
    mm_all<0><<<dim3(108, 2, 1), 256, DSMEM_SZ>>>(nullptr, nullptr);

    // 4. merged winograd (3-term) + vproj (2-term) GEMM  <-- ncu capture slot
    mm_all<1><<<dim3(NT * 6 + 86, 1, BATCH), 256, DSMEM_SZ>>>(nullptr, nullptr);

    // 5. fused F(4,3) output transform + sampling
    wgSample<<<dim3(NTILE, BATCH), 512>>>();

    // 6. output projection + residual + BN + SiLU
    mm_all<3><<<dim3(32, 2, BATCH), 256, DSMEM_SZ>>>(query, out);
}

// round 15
// speedup vs baseline: 1.1106x; 1.0432x over previous
#include <cuda_runtime.h>
#include <cuda_fp16.h>
#include <math.h>
#include <stdint.h>

// ---------------------------------------------------------------------------
// Problem constants
// ---------------------------------------------------------------------------
#define BATCH   4
#define HW      4096
#define BN_EPS  1e-5f
#define VPIX    5440
#define VSTRF   (VPIX*256)
#define WROW    512                  // split row: [256 hi][256 lo] fp16
#define AROW    256                  // plain activation row: 256 fp16
#define NT      36                   // winograd F(4,3): 6x6 transform points
#define NTILE   256                  // 16x16 tiles of 4x4 output per image

__device__ __constant__ int c_voff[4] = {0, 1048576, 1310720, 1376256};
__device__ __constant__ int c_vpix[4] = {0, 4096, 5120, 5376};
__device__ __constant__ int c_mact[4] = {4096, 1024, 256, 64};
__device__ __constant__ int c_vts[5]  = {0, 32, 40, 42, 43};
__device__ __constant__ int c_ftk[5]  = {0, 128, 160, 168, 170};
__constant__ float G6[6][3] = {
    {0.25f, 0.f, 0.f},
    {-1.f/6.f, -1.f/6.f, -1.f/6.f},
    {-1.f/6.f,  1.f/6.f, -1.f/6.f},
    {1.f/24.f,  1.f/12.f, 1.f/6.f},
    {1.f/24.f, -1.f/12.f, 1.f/6.f},
    {0.f, 0.f, 1.f}};

// ---------------------------------------------------------------------------
// Scratch
// ---------------------------------------------------------------------------
__device__ __half g_fT [BATCH * VPIX * AROW];      // feats fp16
__device__ __half g_att[BATCH * HW * AROW];        // sampler out fp16
__device__ __half g_qwT[256 * WROW];               // q_w^T split
__device__ __half g_vw [4 * 256 * WROW];           // v_w split
__device__ __half g_ow [256 * WROW];               // out_w split
__device__ __half g_W2 [NT * 384 * WROW];          // G-transformed conv w split
__device__ __half g_Uw [NT * 384 * WROW];          // winograd weights split
__device__ __half g_V  [(long)NT * 4 * NTILE * WROW]; // winograd input transform split
__device__ float g_M  [(long)NT * 4 * NTILE * 384];   // winograd GEMM out fp32
__device__ __half g_v  [BATCH * VSTRF];            // values fp16 channel-last
__device__ float g_cb [384];
__device__ float g_bns[256], g_bnb[256];

// ---------------------------------------------------------------------------
// Helpers
// ---------------------------------------------------------------------------
__device__ __forceinline__ uint32_t smem_u32(const void* p) {
    uint32_t a;
    asm("{ .reg .u64 t; cvta.to.shared.u64 t, %1; cvt.u32.u64 %0, t; }"
        : "=r"(a) : "l"(p));
    return a;
}
__device__ __forceinline__ void cp16(uint32_t dst, const void* src, bool v) {
    int sz = v ? 16 : 0;
    asm volatile("cp.async.cg.shared.global [%0], [%1], 16, %2;\n"
                 :: "r"(dst), "l"(src), "r"(sz) : "memory");
}
__device__ __forceinline__ void cp_commit() {
    asm volatile("cp.async.commit_group;\n" ::: "memory");
}
__device__ __forceinline__ void cp_wait1() {
    asm volatile("cp.async.wait_group 1;\n" ::: "memory");
}
__device__ __forceinline__ void mma_f16(float* c, const uint32_t* a, const uint32_t* b) {
    asm volatile(
        "mma.sync.aligned.m16n8k16.row.col.f32.f16.f16.f32 "
        "{%0,%1,%2,%3}, {%4,%5,%6,%7}, {%8,%9}, {%0,%1,%2,%3};"
        : "+f"(c[0]), "+f"(c[1]), "+f"(c[2]), "+f"(c[3])
        : "r"(a[0]), "r"(a[1]), "r"(a[2]), "r"(a[3]), "r"(b[0]), "r"(b[1]));
}
#define LDSM_X4(r0, r1, r2, r3, addr) \
    asm volatile("ldmatrix.sync.aligned.m8n8.x4.shared.b16 {%0,%1,%2,%3}, [%4];" \
        : "=r"(r0), "=r"(r1), "=r"(r2), "=r"(r3) : "r"(addr))

__device__ __forceinline__ void split_h(float x, __half& h, __half& l) {
    h = __float2half_rn(x);
    l = __float2half_rn(x - __half2float(h));
}
__device__ __forceinline__ float silu(float x) {
    return x / (1.f + expf(-x));
}

#define STG_B    16384
#define DSMEM_SZ (6 * STG_B)          // 96 KB -> 2 CTAs/SM

// ---------------------------------------------------------------------------
// Unified fp16 GEMM, K=256 (NK=8), D[128m][128n] = sum_k A[m][k]*B[n][k].
// LM 0: compose  (A split 3-term; rows 36*384)
// LM 1: merged winograd (A=V split, 3-term) + vproj (A=fT plain, 2-term)
// LM 3: outproj (+resid, BN, SiLU) with smem-staged coalesced epilogue
// ---------------------------------------------------------------------------
template<int LM>
__global__ __launch_bounds__(256, 2)
void mm_all(const float* __restrict__ resid, float* __restrict__ outp)
{
    extern __shared__ float sm[];

    const int b    = blockIdx.z;
    const int tid  = threadIdx.x;
    const int wid  = tid >> 5;
    const int lane = tid & 31;
    const int wm   = wid >> 2;
    const int wn   = wid & 3;
    const int gid  = lane >> 2;
    const int tig  = lane & 3;
    const int l8   = lane & 7;
    const int lm   = (lane >> 3) & 1;
    const int lh   = lane >> 4;

    // ---- per-CTA mode & geometry ----
    int mode, m0, n0, lvl = 0, M_act = 1 << 30;
    long mBase = 0;
    const __half *Abase, *Bbase;
    if (LM == 1) {
        int idx = blockIdx.x;
        if (idx < NT * 6) {          // 36 t * (2 m-tiles x 3 n-tiles)
            mode = 1;
            int t = idx / 6, sub = idx % 6;
            m0 = (sub & 1) * 128; n0 = (sub >> 1) * 128;
            Abase = g_V + ((long)(t * 4 + b) * NTILE) * WROW;
            Bbase = g_Uw + (long)t * 384 * WROW;
            mBase = ((long)(t * 4 + b) * NTILE) * 384;
            M_act = NTILE;
        } else {
            mode = 2; int tv = idx - NT * 6;
            int nt = (tv >= 43) ? 1 : 0;
            int mtile = tv - nt * 43;
            while (mtile >= c_vts[lvl + 1]) lvl++;
            m0 = (mtile - c_vts[lvl]) * 128;
            n0 = nt * 128;
            M_act = c_mact[lvl];
            Abase = g_fT + (long)b * VPIX * AROW + (long)c_vpix[lvl] * AROW;
            Bbase = g_vw + lvl * 256 * WROW;
        }
    } else if (LM == 0) {
        mode = 0; m0 = blockIdx.x * 128; n0 = blockIdx.y * 128;
        Abase = g_W2; Bbase = g_qwT;
        M_act = NT * 384;            // 13824 = 108*128 exact
    } else {
        mode = 3; m0 = blockIdx.x * 128; n0 = blockIdx.y * 128;
        Abase = g_att + (long)b * HW * AROW; Bbase = g_ow;
        M_act = 4096;
    }
    const bool splitA = (LM == 0) || (LM == 1 && mode == 1);

    // ---- hoisted loader state ----
    const int r0    = tid >> 3;
    const int sub   = tid & 7;
    const int plane = sub >> 2;
    const int kc    = sub & 3;
    const int phys  = sub ^ (r0 & 7);
    const uint32_t smb = smem_u32(sm);

    const __half* aBW = Abase + (long)(m0 + r0) * WROW + plane * 256 + kc * 8;
    const __half* aBA = Abase + (long)(m0 + r0) * AROW + sub * 8;
    const __half* bP  = Bbase + (long)(n0 + r0) * WROW + plane * 256 + kc * 8;
    const uint32_t dA0 = smb + r0 * 128 + phys * 16;
    const uint32_t dB0 = dA0 + 3 * STG_B;

    bool aOK[4];
#pragma unroll
    for (int i = 0; i < 4; i++) aOK[i] = (m0 + r0 + 32 * i) < M_act;

    float acc[4][4][4];
#pragma unroll
    for (int mt = 0; mt < 4; mt++)
#pragma unroll
        for (int nt = 0; nt < 4; nt++)
#pragma unroll
            for (int r = 0; r < 4; r++) acc[mt][nt][r] = 0.f;

    auto load_stage = [&](int s, int buf) {
        const __half* bp = bP + s * 32;
        const uint32_t dB = dB0 + buf * STG_B;
#pragma unroll
        for (int i = 0; i < 4; i++)
            cp16(dB + i * 4096, bp + i * 32 * WROW, true);
        const uint32_t dA = dA0 + buf * STG_B;
        if (splitA) {
            const __half* ap = aBW + s * 32;
#pragma unroll
            for (int i = 0; i < 4; i++)
                cp16(dA + i * 4096, aOK[i] ? (ap + i * 32 * WROW) : (const void*)Abase, aOK[i]);
        } else if (sub < 4) {
            const __half* ap = aBA + s * 32;
#pragma unroll
            for (int i = 0; i < 4; i++)
                cp16(dA + i * 4096, aOK[i] ? (ap + i * 32 * AROW) : (const void*)Abase, aOK[i]);
        }
    };

    load_stage(0, 0); cp_commit();
    load_stage(1, 1); cp_commit();

    for (int s = 0; s < 8; s++) {
        const int buf = s % 3;
        cp_wait1();
        __syncthreads();
        if (s + 2 < 8) { load_stage(s + 2, (s + 2) % 3); }
        cp_commit();

        const uint32_t aBase_s = smb + buf * STG_B;
        const uint32_t bBase_s = smb + (3 + buf) * STG_B;
#pragma unroll
        for (int kk = 0; kk < 2; kk++) {
            const int chH = kk * 2 + lh;
            const int chL = chH + 4;
            uint32_t ah[4][4], al[4][4], bh[4][2], bl[4][2];
#pragma unroll
            for (int mt = 0; mt < 4; mt++) {
                int row = wm * 64 + mt * 16 + l8 + lm * 8;
                uint32_t base = aBase_s + row * 128;
                LDSM_X4(ah[mt][0], ah[mt][1], ah[mt][2], ah[mt][3],
                        base + ((chH ^ l8) << 4));
                if (splitA)
                    LDSM_X4(al[mt][0], al[mt][1], al[mt][2], al[mt][3],
                            base + ((chL ^ l8) << 4));
            }
#pragma unroll
            for (int np = 0; np < 2; np++) {
                int row = wn * 32 + np * 16 + l8 + lm * 8;
                uint32_t base = bBase_s + row * 128;
                LDSM_X4(bh[2 * np][0], bh[2 * np + 1][0],
                        bh[2 * np][1], bh[2 * np + 1][1],
                        base + ((chH ^ l8) << 4));
                LDSM_X4(bl[2 * np][0], bl[2 * np + 1][0],
                        bl[2 * np][1], bl[2 * np + 1][1],
                        base + ((chL ^ l8) << 4));
            }
            if (splitA) {
#pragma unroll
                for (int mt = 0; mt < 4; mt++)
#pragma unroll
                    for (int nt = 0; nt < 4; nt++) {
                        mma_f16(acc[mt][nt], ah[mt], bh[nt]);
                        mma_f16(acc[mt][nt], ah[mt], bl[nt]);
                        mma_f16(acc[mt][nt], al[mt], bh[nt]);
                    }
            } else {
#pragma unroll
                for (int mt = 0; mt < 4; mt++)
#pragma unroll
                    for (int nt = 0; nt < 4; nt++) {
                        mma_f16(acc[mt][nt], ah[mt], bh[nt]);
                        mma_f16(acc[mt][nt], ah[mt], bl[nt]);
                    }
            }
        }
    }

    // ---- epilogues ----
    if (LM != 3) {
#pragma unroll
        for (int mt = 0; mt < 4; mt++) {
            int r0e = m0 + wm * 64 + mt * 16 + gid;
#pragma unroll
            for (int nt = 0; nt < 4; nt++) {
                int col = n0 + wn * 32 + nt * 8 + tig * 2;
#pragma unroll
                for (int h = 0; h < 2; h++) {
                    int r = r0e + h * 8;
                    float vx = acc[mt][nt][2 * h];
                    float vy = acc[mt][nt][2 * h + 1];
                    if (mode == 0) {
                        long e = (long)r * WROW + col;
                        __half hh, ll;
                        split_h(vx, hh, ll); g_Uw[e]     = hh; g_Uw[e + 256]     = ll;
                        split_h(vy, hh, ll); g_Uw[e + 1] = hh; g_Uw[e + 1 + 256] = ll;
                    } else if (mode == 1) {
                        if (r < M_act)
                            *(float2*)&g_M[mBase + (long)r * 384 + col] = make_float2(vx, vy);
                    } else {
                        if (r < M_act) {
                            long row = c_vpix[lvl] + r;
                            *(__half2*)&g_v[(long)b * VSTRF + row * 256 + col] =
                                __floats2half2_rn(vx, vy);
                        }
                    }
                }
            }
        }
    } else {
        // stage tile to smem [ocLocal][132] then coalesced float4 I/O
        __syncthreads();
        float* sf = sm;
#pragma unroll
        for (int mt = 0; mt < 4; mt++) {
            int rl0 = wm * 64 + mt * 16 + gid;
#pragma unroll
            for (int nt = 0; nt < 4; nt++) {
                int cl = wn * 32 + nt * 8 + tig * 2;
#pragma unroll
                for (int h = 0; h < 2; h++) {
                    int rl = rl0 + h * 8;
                    sf[(cl)     * 132 + rl] = acc[mt][nt][2 * h];
                    sf[(cl + 1) * 132 + rl] = acc[mt][nt][2 * h + 1];
                }
            }
        }
        __syncthreads();
        const float* qb = resid + (long)b * 256 * HW;
        float* yb = outp + (long)b * 256 * HW;
        for (int i = tid; i < 128 * 32; i += 256) {
            int ocl = i >> 5;            // 0..127
            int r4  = i & 31;            // 0..31
            int oc  = n0 + ocl;
            int rg  = m0 + r4 * 4;
            float4 qv = *(const float4*)&qb[(long)oc * HW + rg];
            float4 o;
            o.x = silu((sf[ocl * 132 + r4 * 4 + 0] + qv.x) * g_bns[oc] + g_bnb[oc]);
            o.y = silu((sf[ocl * 132 + r4 * 4 + 1] + qv.y) * g_bns[oc] + g_bnb[oc]);
            o.z = silu((sf[ocl * 132 + r4 * 4 + 2] + qv.z) * g_bns[oc] + g_bnb[oc]);
            o.w = silu((sf[ocl * 132 + r4 * 4 + 3] + qv.w) * g_bns[oc] + g_bnb[oc]);
            *(float4*)&yb[(long)oc * HW + rg] = o;
        }
    }
}

// ---------------------------------------------------------------------------
// Merged prep: feat transposes (x<170) + F(4,3) input transform (x in [170,202))
// + ALL weight prep (x >= 202, flattened over y,z).
// ---------------------------------------------------------------------------
__global__ __launch_bounds__(256)
void prepActs(const float* __restrict__ q,
              const float* __restrict__ f0, const float* __restrict__ f1,
              const float* __restrict__ f2, const float* __restrict__ f3,
              const float* __restrict__ qw, const float* __restrict__ vw,
              const float* __restrict__ ow,
              const float* __restrict__ offw, const float* __restrict__ attw,
              const float* __restrict__ offb, const float* __restrict__ attb,
              const float* __restrict__ bg, const float* __restrict__ bb,
              const float* __restrict__ bm, const float* __restrict__ bv)
{
    __shared__ float tbuf[32][33];
    __shared__ float s[6][34][32];
    const int b = blockIdx.z;
    const int tid = threadIdx.x;

    if (blockIdx.x < 170) {
        int lvl = 0;
        while ((int)blockIdx.x >= c_ftk[lvl + 1]) lvl++;
        const int P  = c_mact[lvl];
        const int p0 = (blockIdx.x - c_ftk[lvl]) * 32;
        const float* I = (lvl == 0 ? f0 : lvl == 1 ? f1 : lvl == 2 ? f2 : f3)
                       + (long)b * 256 * P;
        __half* Of = g_fT + (long)b * VPIX * AROW + (long)c_vpix[lvl] * AROW;
        const int c0 = blockIdx.y * 32;
        const int tx = tid & 31, ty = tid >> 5;
#pragma unroll
        for (int i = 0; i < 32; i += 8)
            tbuf[ty + i][tx] = I[(long)(c0 + ty + i) * P + p0 + tx];
        __syncthreads();
#pragma unroll
        for (int i = 0; i < 32; i += 8)
            Of[(long)(p0 + ty + i) * AROW + c0 + tx] = __float2half_rn(tbuf[tx][ty + i]);
    } else if (blockIdx.x < 202) {
        const int e   = blockIdx.x - 170;   // 0..31
        const int ty  = e >> 1;             // tile row 0..15
        const int txg = (e & 1) * 8;        // first tile col of this block
        const int cg  = blockIdx.y;         // 0..7
        for (int idx = tid; idx < 6 * 34 * 32; idx += 256) {
            int cc  = idx / 204;
            int rem = idx - cc * 204;
            int row = rem / 34;
            int col = rem - row * 34;
            int gy = 4 * ty - 1 + row;
            int gx = 4 * txg - 1 + col;
            float v = 0.f;
            if (gy >= 0 && gy < 64 && gx >= 0 && gx < 64)
                v = q[((long)b * 256 + cg * 32 + cc) * 4096 + gy * 64 + gx];
            s[row][col][cc] = v;
        }
        __syncthreads();
        const int lane = tid & 31, w = tid >> 5;   // 8 warps = 8 tiles
        float d[6][6];
#pragma unroll
        for (int i = 0; i < 6; i++)
#pragma unroll
            for (int j = 0; j < 6; j++) d[i][j] = s[i][4 * w + j][lane];
        float t1[6][6];
#pragma unroll
        for (int j = 0; j < 6; j++) {
            t1[0][j] = 4.f * d[0][j] - 5.f * d[2][j] + d[4][j];
            t1[1][j] = -4.f * d[1][j] - 4.f * d[2][j] + d[3][j] + d[4][j];
            t1[2][j] =  4.f * d[1][j] - 4.f * d[2][j] - d[3][j] + d[4][j];
            t1[3][j] = -2.f * d[1][j] - d[2][j] + 2.f * d[3][j] + d[4][j];
            t1[4][j] =  2.f * d[1][j] - d[2][j] - 2.f * d[3][j] + d[4][j];
            t1[5][j] =  4.f * d[1][j] - 5.f * d[3][j] + d[5][j];
        }
        float V[6][6];
#pragma unroll
        for (int i = 0; i < 6; i++) {
            V[i][0] = 4.f * t1[i][0] - 5.f * t1[i][2] + t1[i][4];
            V[i][1] = -4.f * t1[i][1] - 4.f * t1[i][2] + t1[i][3] + t1[i][4];
            V[i][2] =  4.f * t1[i][1] - 4.f * t1[i][2] - t1[i][3] + t1[i][4];
            V[i][3] = -2.f * t1[i][1] - t1[i][2] + 2.f * t1[i][3] + t1[i][4];
            V[i][4] =  2.f * t1[i][1] - t1[i][2] - 2.f * t1[i][3] + t1[i][4];
            V[i][5] =  4.f * t1[i][1] - 5.f * t1[i][3] + t1[i][5];
        }
        const int tile = ty * 16 + txg + w;
#pragma unroll
        for (int i = 0; i < 6; i++)
#pragma unroll
            for (int j = 0; j < 6; j++) {
                int t = i * 6 + j;
                __half h, l;
                split_h(V[i][j], h, l);
                long base = ((long)(t * 4 + b) * NTILE + tile) * WROW + cg * 32 + lane;
                g_V[base] = h; g_V[base + 256] = l;
            }
    } else {
        // ---- weight prep, flattened block id ----
        const int bid = (((int)blockIdx.x - 202) * 8 + (int)blockIdx.y) * 4 + b;
        if (bid < 1024) {                      // v_w -> g_vw split
            long i = (long)bid * 256 + tid;    // < 262144
            long l = i >> 16, rem = i & 65535;
            long o = rem >> 8, c = rem & 255;
            __half h, lo;
            split_h(vw[i], h, lo);
            long e = l * (256 * WROW) + o * WROW + c;
            g_vw[e] = h; g_vw[e + 256] = lo;
        } else if (bid < 1280) {               // out_w -> g_ow split
            long j = (long)(bid - 1024) * 256 + tid;
            long o = j >> 8, c = j & 255;
            __half h, lo;
            split_h(ow[j], h, lo);
            g_ow[o * WROW + c] = h; g_ow[o * WROW + c + 256] = lo;
        } else if (bid < 1536) {               // q_w^T -> g_qwT split
            long j = (long)(bid - 1280) * 256 + tid;
            long c = j >> 8, m = j & 255;
            __half h, lo;
            split_h(qw[m * 256 + c], h, lo);
            g_qwT[c * WROW + m] = h; g_qwT[c * WROW + m + 256] = lo;
        } else if (bid < 1920) {               // G-transform, one block per oc
            const int o = bid - 1536;          // 0..383
            const int m = tid;                 // 0..255
            const float* wsrc = (o < 256) ? offw + ((long)o * 256 + m) * 9
                                          : attw + ((long)(o - 256) * 256 + m) * 9;
            float w9[9];
#pragma unroll
            for (int k = 0; k < 9; k++) w9[k] = wsrc[k];
            float gw[6][3];
#pragma unroll
            for (int i = 0; i < 6; i++)
#pragma unroll
                for (int c = 0; c < 3; c++)
                    gw[i][c] = G6[i][0] * w9[c] + G6[i][1] * w9[3 + c] + G6[i][2] * w9[6 + c];
#pragma unroll
            for (int ti = 0; ti < 6; ti++)
#pragma unroll
                for (int tj = 0; tj < 6; tj++) {
                    float a = gw[ti][0] * G6[tj][0] + gw[ti][1] * G6[tj][1]
                            + gw[ti][2] * G6[tj][2];
                    __half h, lo;
                    split_h(a, h, lo);
                    long e = ((long)(ti * 6 + tj) * 384 + o) * WROW + m;
                    g_W2[e] = h; g_W2[e + 256] = lo;
                }
        } else if (bid == 1920) {              // biases + bn
            if (tid < 384)
                g_cb[tid] = (tid < 256) ? offb[tid] : attb[tid - 256];
            if (tid < 256) {
                float sc = bg[tid] * rsqrtf(bv[tid] + BN_EPS);
                g_bns[tid] = sc;
                g_bnb[tid] = bb[tid] - bm[tid] * sc;
            }
        }
    }
}

// ---------------------------------------------------------------------------
// Fused F(4,3) winograd output transform + deformable sampling.
// ---------------------------------------------------------------------------
__global__ __launch_bounds__(512)
void wgSample()
{
    __shared__ float scv[16][384];
    const int tile = blockIdx.x;
    const int b    = blockIdx.y;
    const int tid  = threadIdx.x;

    if (tid < 384) {
        const int oc = tid;
        const long tstr = (long)4 * NTILE * 384;
        const long base = ((long)b * NTILE + tile) * 384 + oc;
        float m[6][6];
#pragma unroll
        for (int t = 0; t < NT; t++)
            m[t / 6][t % 6] = g_M[(long)t * tstr + base];
        float tp[4][6];
#pragma unroll
        for (int j = 0; j < 6; j++) {
            tp[0][j] = m[0][j] + m[1][j] + m[2][j] + m[3][j] + m[4][j];
            tp[1][j] = m[1][j] - m[2][j] + 2.f * m[3][j] - 2.f * m[4][j];
            tp[2][j] = m[1][j] + m[2][j] + 4.f * m[3][j] + 4.f * m[4][j];
            tp[3][j] = m[1][j] - m[2][j] + 8.f * m[3][j] - 8.f * m[4][j] + m[5][j];
        }
        const float bs = g_cb[oc];
#pragma unroll
        for (int r = 0; r < 4; r++) {
            float y0 = tp[r][0] + tp[r][1] + tp[r][2] + tp[r][3] + tp[r][4];
            float y1 = tp[r][1] - tp[r][2] + 2.f * tp[r][3] - 2.f * tp[r][4];
            float y2 = tp[r][1] + tp[r][2] + 4.f * tp[r][3] + 4.f * tp[r][4];
            float y3 = tp[r][1] - tp[r][2] + 8.f * tp[r][3] - 8.f * tp[r][4] + tp[r][5];
            scv[r * 4 + 0][oc] = y0 + bs;
            scv[r * 4 + 1][oc] = y1 + bs;
            scv[r * 4 + 2][oc] = y2 + bs;
            scv[r * 4 + 3][oc] = y3 + bs;
        }
    }
    __syncthreads();

    const int warp = tid >> 5;
    const int lane = tid & 31;
    const int ty = tile >> 4, tx = tile & 15;
    const int pxl = warp;
    const int py  = 4 * ty + (pxl >> 2);
    const int px  = 4 * tx + (pxl & 3);
    const int pix = py * 64 + px;
    const float refx = -1.f + 2.f * (float)px / 63.f;
    const float refy = -1.f + 2.f * (float)py / 63.f;

    for (int h = 0; h < 8; h++) {
        float lg = -INFINITY, ox = 0.f, oy = 0.f;
        if (lane < 16) {
            lg = scv[pxl][256 + h * 16 + lane];
            ox = tanhf(scv[pxl][h * 32 + 2 * lane    ]) * 0.25f;
            oy = tanhf(scv[pxl][h * 32 + 2 * lane + 1]) * 0.25f;
        }
        float mx = lg;
#pragma unroll
        for (int s = 16; s > 0; s >>= 1)
            mx = fmaxf(mx, __shfl_xor_sync(0xFFFFFFFFu, mx, s));
        float e = (lane < 16) ? expf(lg - mx) : 0.f;
        float sum = e;
#pragma unroll
        for (int s = 16; s > 0; s >>= 1)
            sum += __shfl_xor_sync(0xFFFFFFFFu, sum, s);
        float wgt = e / sum;

        const __half* vb = g_v + (long)b * VSTRF + h * 32 + lane;
        float acc = 0.f;
#pragma unroll
        for (int i = 0; i < 16; i++) {
            const int lvl = i >> 2;
            const int sz  = 64 >> lvl;
            float aw = __shfl_sync(0xFFFFFFFFu, wgt, i);
            float gx = refx + __shfl_sync(0xFFFFFFFFu, ox, i);
            float gy = refy + __shfl_sync(0xFFFFFFFFu, oy, i);

            float xf = (gx + 1.f) * 0.5f * (float)(sz - 1);
            float yf = (gy + 1.f) * 0.5f * (float)(sz - 1);
            float x0f = floorf(xf), y0f = floorf(yf);
            int x0 = (int)x0f, y0 = (int)y0f;
            int x1 = x0 + 1,  y1 = y0 + 1;
            float wx1 = xf - x0f, wx0 = 1.f - wx1;
            float wy1 = yf - y0f, wy0 = 1.f - wy1;

            const __half* vl = vb + c_voff[lvl];
            if (x0 >= 0 && x0 < sz && y0 >= 0 && y0 < sz)
                acc = fmaf(aw * wx0 * wy0, __half2float(vl[(y0 * sz + x0) * 256]), acc);
            if (x1 >= 0 && x1 < sz && y0 >= 0 && y0 < sz)
                acc = fmaf(aw * wx1 * wy0, __half2float(vl[(y0 * sz + x1) * 256]), acc);
            if (x0 >= 0 && x0 < sz && y1 >= 0 && y1 < sz)
                acc = fmaf(aw * wx0 * wy1, __half2float(vl[(y1 * sz + x0) * 256]), acc);
            if (x1 >= 0 && x1 < sz && y1 >= 0 && y1 < sz)
                acc = fmaf(aw * wx1 * wy1, __half2float(vl[(y1 * sz + x1) * 256]), acc);
        }

        g_att[((long)b * HW + pix) * AROW + h * 32 + lane] = __float2half_rn(acc);
    }
}

// ---------------------------------------------------------------------------
// Launch. wgSample is the 4th launch (ncu capture slot).
// ---------------------------------------------------------------------------
extern "C" void kernel_launch(void* const* d_in, const int* in_sizes, int n_in,
                              void* d_out, int out_size)
{
    const float* query  = (const float*)d_in[0];
    const float* feat0  = (const float*)d_in[1];
    const float* feat1  = (const float*)d_in[2];
    const float* feat2  = (const float*)d_in[3];
    const float* feat3  = (const float*)d_in[4];
    const float* q_w    = (const float*)d_in[5];
    const float* v_w    = (const float*)d_in[6];
    const float* out_w  = (const float*)d_in[7];
    const float* off_w  = (const float*)d_in[8];
    const float* off_b  = (const float*)d_in[9];
    const float* attn_w = (const float*)d_in[10];
    const float* attn_b = (const float*)d_in[11];
    const float* bn_g   = (const float*)d_in[12];
    const float* bn_b   = (const float*)d_in[13];
    const float* bn_m   = (const float*)d_in[14];
    const float* bn_v   = (const float*)d_in[15];
    float* out = (float*)d_out;

    cudaFuncSetAttribute(mm_all<0>, cudaFuncAttributeMaxDynamicSharedMemorySize, DSMEM_SZ);
    cudaFuncSetAttribute(mm_all<1>, cudaFuncAttributeMaxDynamicSharedMemorySize, DSMEM_SZ);
    cudaFuncSetAttribute(mm_all<3>, cudaFuncAttributeMaxDynamicSharedMemorySize, DSMEM_SZ);

    // 1. all prep: feat transposes + F(4,3) input transform + weight prep
    prepActs<<<dim3(263, 8, BATCH), 256>>>(query, feat0, feat1, feat2, feat3,
                                           q_w, v_w, out_w, off_w, attn_w,
                                           off_b, attn_b, bn_g, bn_b, bn_m, bn_v);

    // 2. compose winograd weights (3-term)
    mm_all<0><<<dim3(108, 2, 1), 256, DSMEM_SZ>>>(nullptr, nullptr);

    // 3. merged winograd (3-term) + vproj (2-term) GEMM
    mm_all<1><<<dim3(NT * 6 + 86, 1, BATCH), 256, DSMEM_SZ>>>(nullptr, nullptr);

    // 4. fused F(4,3) output transform + sampling   <-- ncu capture slot
    wgSample<<<dim3(NTILE, BATCH), 512>>>();

    // 5. output projection + residual + BN + SiLU (coalesced epilogue)
    mm_all<3><<<dim3(32, 2, BATCH), 256, DSMEM_SZ>>>(query, out);
}

// round 16
// speedup vs baseline: 1.3347x; 1.2019x over previous
#include <cuda_runtime.h>
#include <cuda_fp16.h>
#include <math.h>
#include <stdint.h>

// ---------------------------------------------------------------------------
// Problem constants
// ---------------------------------------------------------------------------
#define BATCH   4
#define HW      4096
#define BN_EPS  1e-5f
#define VPIX    5440
#define VSTRF   (VPIX*256)
#define WROW    512                  // split row: [256 hi][256 lo] fp16
#define AROW    256                  // plain activation row: 256 fp16
#define NT      36                   // winograd F(4,3): 6x6 transform points
#define NTILE   256                  // 16x16 tiles of 4x4 output per image

__device__ __constant__ int c_voff[4] = {0, 1048576, 1310720, 1376256};
__device__ __constant__ int c_vpix[4] = {0, 4096, 5120, 5376};
__device__ __constant__ int c_mact[4] = {4096, 1024, 256, 64};
__device__ __constant__ int c_vts[5]  = {0, 32, 40, 42, 43};
__device__ __constant__ int c_ftk[5]  = {0, 128, 160, 168, 170};
__constant__ float G6[6][3] = {
    {0.25f, 0.f, 0.f},
    {-1.f/6.f, -1.f/6.f, -1.f/6.f},
    {-1.f/6.f,  1.f/6.f, -1.f/6.f},
    {1.f/24.f,  1.f/12.f, 1.f/6.f},
    {1.f/24.f, -1.f/12.f, 1.f/6.f},
    {0.f, 0.f, 1.f}};

// ---------------------------------------------------------------------------
// Scratch
// ---------------------------------------------------------------------------
__device__ __half g_fT [BATCH * VPIX * AROW];      // feats fp16
__device__ __half g_att[BATCH * HW * AROW];        // sampler out fp16
__device__ __half g_qwT[256 * WROW];               // q_w^T split
__device__ __half g_vw [4 * 256 * WROW];           // v_w split
__device__ __half g_ow [256 * WROW];               // out_w split
__device__ __half g_W2 [NT * 384 * WROW];          // G-transformed conv w split
__device__ __half g_Uw [NT * 384 * WROW];          // winograd weights split
__device__ __half g_V  [(long)NT * 4 * NTILE * WROW]; // winograd input transform split
__device__ float g_M  [(long)NT * 4 * NTILE * 384];   // winograd GEMM out fp32
__device__ __half g_v  [BATCH * VSTRF];            // values fp16 channel-last
__device__ float g_cb [384];
__device__ float g_bns[256], g_bnb[256];

// ---------------------------------------------------------------------------
// Helpers
// ---------------------------------------------------------------------------
__device__ __forceinline__ uint32_t smem_u32(const void* p) {
    uint32_t a;
    asm("{ .reg .u64 t; cvta.to.shared.u64 t, %1; cvt.u32.u64 %0, t; }"
        : "=r"(a) : "l"(p));
    return a;
}
__device__ __forceinline__ void cp16(uint32_t dst, const void* src, bool v) {
    int sz = v ? 16 : 0;
    asm volatile("cp.async.cg.shared.global [%0], [%1], 16, %2;\n"
                 :: "r"(dst), "l"(src), "r"(sz) : "memory");
}
__device__ __forceinline__ void cp_commit() {
    asm volatile("cp.async.commit_group;\n" ::: "memory");
}
__device__ __forceinline__ void cp_wait1() {
    asm volatile("cp.async.wait_group 1;\n" ::: "memory");
}
__device__ __forceinline__ void mma_f16(float* c, const uint32_t* a, const uint32_t* b) {
    asm volatile(
        "mma.sync.aligned.m16n8k16.row.col.f32.f16.f16.f32 "
        "{%0,%1,%2,%3}, {%4,%5,%6,%7}, {%8,%9}, {%0,%1,%2,%3};"
        : "+f"(c[0]), "+f"(c[1]), "+f"(c[2]), "+f"(c[3])
        : "r"(a[0]), "r"(a[1]), "r"(a[2]), "r"(a[3]), "r"(b[0]), "r"(b[1]));
}
#define LDSM_X4(r0, r1, r2, r3, addr) \
    asm volatile("ldmatrix.sync.aligned.m8n8.x4.shared.b16 {%0,%1,%2,%3}, [%4];" \
        : "=r"(r0), "=r"(r1), "=r"(r2), "=r"(r3) : "r"(addr))

__device__ __forceinline__ void split_h(float x, __half& h, __half& l) {
    h = __float2half_rn(x);
    l = __float2half_rn(x - __half2float(h));
}
__device__ __forceinline__ float silu(float x) {
    return x / (1.f + expf(-x));
}

#define STG_B    16384
#define DSMEM_SZ (6 * STG_B)          // 96 KB -> 2 CTAs/SM

// ---------------------------------------------------------------------------
// Unified fp16 GEMM, K=256 (NK=8), D[128m][128n] = sum_k A[m][k]*B[n][k].
// LM 0: compose  (A split 3-term; rows 36*384)
// LM 1: merged winograd (A=V split, 3-term) + vproj (A=fT plain, 2-term)
// LM 3: outproj (+resid, BN, SiLU) with smem-staged coalesced epilogue
// ---------------------------------------------------------------------------
template<int LM>
__global__ __launch_bounds__(256, 2)
void mm_all(const float* __restrict__ resid, float* __restrict__ outp)
{
    extern __shared__ float sm[];

    const int b    = blockIdx.z;
    const int tid  = threadIdx.x;
    const int wid  = tid >> 5;
    const int lane = tid & 31;
    const int wm   = wid >> 2;
    const int wn   = wid & 3;
    const int gid  = lane >> 2;
    const int tig  = lane & 3;
    const int l8   = lane & 7;
    const int lm   = (lane >> 3) & 1;
    const int lh   = lane >> 4;

    // ---- per-CTA mode & geometry ----
    int mode, m0, n0, lvl = 0, M_act = 1 << 30;
    long mBase = 0;
    const __half *Abase, *Bbase;
    if (LM == 1) {
        int idx = blockIdx.x;
        if (idx < NT * 6) {
            mode = 1;
            int t = idx / 6, sub = idx % 6;
            m0 = (sub & 1) * 128; n0 = (sub >> 1) * 128;
            Abase = g_V + ((long)(t * 4 + b) * NTILE) * WROW;
            Bbase = g_Uw + (long)t * 384 * WROW;
            mBase = ((long)(t * 4 + b) * NTILE) * 384;
            M_act = NTILE;
        } else {
            mode = 2; int tv = idx - NT * 6;
            int nt = (tv >= 43) ? 1 : 0;
            int mtile = tv - nt * 43;
            while (mtile >= c_vts[lvl + 1]) lvl++;
            m0 = (mtile - c_vts[lvl]) * 128;
            n0 = nt * 128;
            M_act = c_mact[lvl];
            Abase = g_fT + (long)b * VPIX * AROW + (long)c_vpix[lvl] * AROW;
            Bbase = g_vw + lvl * 256 * WROW;
        }
    } else if (LM == 0) {
        mode = 0; m0 = blockIdx.x * 128; n0 = blockIdx.y * 128;
        Abase = g_W2; Bbase = g_qwT;
        M_act = NT * 384;
    } else {
        mode = 3; m0 = blockIdx.x * 128; n0 = blockIdx.y * 128;
        Abase = g_att + (long)b * HW * AROW; Bbase = g_ow;
        M_act = 4096;
    }
    const bool splitA = (LM == 0) || (LM == 1 && mode == 1);

    // ---- hoisted loader state ----
    const int r0    = tid >> 3;
    const int sub   = tid & 7;
    const int plane = sub >> 2;
    const int kc    = sub & 3;
    const int phys  = sub ^ (r0 & 7);
    const uint32_t smb = smem_u32(sm);

    const __half* aBW = Abase + (long)(m0 + r0) * WROW + plane * 256 + kc * 8;
    const __half* aBA = Abase + (long)(m0 + r0) * AROW + sub * 8;
    const __half* bP  = Bbase + (long)(n0 + r0) * WROW + plane * 256 + kc * 8;
    const uint32_t dA0 = smb + r0 * 128 + phys * 16;
    const uint32_t dB0 = dA0 + 3 * STG_B;

    bool aOK[4];
#pragma unroll
    for (int i = 0; i < 4; i++) aOK[i] = (m0 + r0 + 32 * i) < M_act;

    float acc[4][4][4];
#pragma unroll
    for (int mt = 0; mt < 4; mt++)
#pragma unroll
        for (int nt = 0; nt < 4; nt++)
#pragma unroll
            for (int r = 0; r < 4; r++) acc[mt][nt][r] = 0.f;

    auto load_stage = [&](int s, int buf) {
        const __half* bp = bP + s * 32;
        const uint32_t dB = dB0 + buf * STG_B;
#pragma unroll
        for (int i = 0; i < 4; i++)
            cp16(dB + i * 4096, bp + i * 32 * WROW, true);
        const uint32_t dA = dA0 + buf * STG_B;
        if (splitA) {
            const __half* ap = aBW + s * 32;
#pragma unroll
            for (int i = 0; i < 4; i++)
                cp16(dA + i * 4096, aOK[i] ? (ap + i * 32 * WROW) : (const void*)Abase, aOK[i]);
        } else if (sub < 4) {
            const __half* ap = aBA + s * 32;
#pragma unroll
            for (int i = 0; i < 4; i++)
                cp16(dA + i * 4096, aOK[i] ? (ap + i * 32 * AROW) : (const void*)Abase, aOK[i]);
        }
    };

    load_stage(0, 0); cp_commit();
    load_stage(1, 1); cp_commit();

    for (int s = 0; s < 8; s++) {
        const int buf = s % 3;
        cp_wait1();
        __syncthreads();
        if (s + 2 < 8) { load_stage(s + 2, (s + 2) % 3); }
        cp_commit();

        const uint32_t aBase_s = smb + buf * STG_B;
        const uint32_t bBase_s = smb + (3 + buf) * STG_B;
#pragma unroll
        for (int kk = 0; kk < 2; kk++) {
            const int chH = kk * 2 + lh;
            const int chL = chH + 4;
            uint32_t ah[4][4], al[4][4], bh[4][2], bl[4][2];
#pragma unroll
            for (int mt = 0; mt < 4; mt++) {
                int row = wm * 64 + mt * 16 + l8 + lm * 8;
                uint32_t base = aBase_s + row * 128;
                LDSM_X4(ah[mt][0], ah[mt][1], ah[mt][2], ah[mt][3],
                        base + ((chH ^ l8) << 4));
                if (splitA)
                    LDSM_X4(al[mt][0], al[mt][1], al[mt][2], al[mt][3],
                            base + ((chL ^ l8) << 4));
            }
#pragma unroll
            for (int np = 0; np < 2; np++) {
                int row = wn * 32 + np * 16 + l8 + lm * 8;
                uint32_t base = bBase_s + row * 128;
                LDSM_X4(bh[2 * np][0], bh[2 * np + 1][0],
                        bh[2 * np][1], bh[2 * np + 1][1],
                        base + ((chH ^ l8) << 4));
                LDSM_X4(bl[2 * np][0], bl[2 * np + 1][0],
                        bl[2 * np][1], bl[2 * np + 1][1],
                        base + ((chL ^ l8) << 4));
            }
            if (splitA) {
#pragma unroll
                for (int mt = 0; mt < 4; mt++)
#pragma unroll
                    for (int nt = 0; nt < 4; nt++) {
                        mma_f16(acc[mt][nt], ah[mt], bh[nt]);
                        mma_f16(acc[mt][nt], ah[mt], bl[nt]);
                        mma_f16(acc[mt][nt], al[mt], bh[nt]);
                    }
            } else {
#pragma unroll
                for (int mt = 0; mt < 4; mt++)
#pragma unroll
                    for (int nt = 0; nt < 4; nt++) {
                        mma_f16(acc[mt][nt], ah[mt], bh[nt]);
                        mma_f16(acc[mt][nt], ah[mt], bl[nt]);
                    }
            }
        }
    }

    // ---- epilogues ----
    if (LM != 3) {
#pragma unroll
        for (int mt = 0; mt < 4; mt++) {
            int r0e = m0 + wm * 64 + mt * 16 + gid;
#pragma unroll
            for (int nt = 0; nt < 4; nt++) {
                int col = n0 + wn * 32 + nt * 8 + tig * 2;
#pragma unroll
                for (int h = 0; h < 2; h++) {
                    int r = r0e + h * 8;
                    float vx = acc[mt][nt][2 * h];
                    float vy = acc[mt][nt][2 * h + 1];
                    if (mode == 0) {
                        long e = (long)r * WROW + col;
                        __half hh, ll;
                        split_h(vx, hh, ll); g_Uw[e]     = hh; g_Uw[e + 256]     = ll;
                        split_h(vy, hh, ll); g_Uw[e + 1] = hh; g_Uw[e + 1 + 256] = ll;
                    } else if (mode == 1) {
                        if (r < M_act)
                            *(float2*)&g_M[mBase + (long)r * 384 + col] = make_float2(vx, vy);
                    } else {
                        if (r < M_act) {
                            long row = c_vpix[lvl] + r;
                            *(__half2*)&g_v[(long)b * VSTRF + row * 256 + col] =
                                __floats2half2_rn(vx, vy);
                        }
                    }
                }
            }
        }
    } else {
        __syncthreads();
        float* sf = sm;
#pragma unroll
        for (int mt = 0; mt < 4; mt++) {
            int rl0 = wm * 64 + mt * 16 + gid;
#pragma unroll
            for (int nt = 0; nt < 4; nt++) {
                int cl = wn * 32 + nt * 8 + tig * 2;
#pragma unroll
                for (int h = 0; h < 2; h++) {
                    int rl = rl0 + h * 8;
                    sf[(cl)     * 132 + rl] = acc[mt][nt][2 * h];
                    sf[(cl + 1) * 132 + rl] = acc[mt][nt][2 * h + 1];
                }
            }
        }
        __syncthreads();
        const float* qb = resid + (long)b * 256 * HW;
        float* yb = outp + (long)b * 256 * HW;
        for (int i = tid; i < 128 * 32; i += 256) {
            int ocl = i >> 5;
            int r4  = i & 31;
            int oc  = n0 + ocl;
            int rg  = m0 + r4 * 4;
            float4 qv = *(const float4*)&qb[(long)oc * HW + rg];
            float4 o;
            o.x = silu((sf[ocl * 132 + r4 * 4 + 0] + qv.x) * g_bns[oc] + g_bnb[oc]);
            o.y = silu((sf[ocl * 132 + r4 * 4 + 1] + qv.y) * g_bns[oc] + g_bnb[oc]);
            o.z = silu((sf[ocl * 132 + r4 * 4 + 2] + qv.z) * g_bns[oc] + g_bnb[oc]);
            o.w = silu((sf[ocl * 132 + r4 * 4 + 3] + qv.w) * g_bns[oc] + g_bnb[oc]);
            *(float4*)&yb[(long)oc * HW + rg] = o;
        }
    }
}

// ---------------------------------------------------------------------------
// Merged prep: feat transposes + F(4,3) input transform + weight prep.
// ---------------------------------------------------------------------------
__global__ __launch_bounds__(256)
void prepActs(const float* __restrict__ q,
              const float* __restrict__ f0, const float* __restrict__ f1,
              const float* __restrict__ f2, const float* __restrict__ f3,
              const float* __restrict__ qw, const float* __restrict__ vw,
              const float* __restrict__ ow,
              const float* __restrict__ offw, const float* __restrict__ attw,
              const float* __restrict__ offb, const float* __restrict__ attb,
              const float* __restrict__ bg, const float* __restrict__ bb,
              const float* __restrict__ bm, const float* __restrict__ bv)
{
    __shared__ float tbuf[32][33];
    __shared__ float s[6][34][32];
    const int b = blockIdx.z;
    const int tid = threadIdx.x;

    if (blockIdx.x < 170) {
        int lvl = 0;
        while ((int)blockIdx.x >= c_ftk[lvl + 1]) lvl++;
        const int P  = c_mact[lvl];
        const int p0 = (blockIdx.x - c_ftk[lvl]) * 32;
        const float* I = (lvl == 0 ? f0 : lvl == 1 ? f1 : lvl == 2 ? f2 : f3)
                       + (long)b * 256 * P;
        __half* Of = g_fT + (long)b * VPIX * AROW + (long)c_vpix[lvl] * AROW;
        const int c0 = blockIdx.y * 32;
        const int tx = tid & 31, ty = tid >> 5;
#pragma unroll
        for (int i = 0; i < 32; i += 8)
            tbuf[ty + i][tx] = I[(long)(c0 + ty + i) * P + p0 + tx];
        __syncthreads();
#pragma unroll
        for (int i = 0; i < 32; i += 8)
            Of[(long)(p0 + ty + i) * AROW + c0 + tx] = __float2half_rn(tbuf[tx][ty + i]);
    } else if (blockIdx.x < 202) {
        const int e   = blockIdx.x - 170;
        const int ty  = e >> 1;
        const int txg = (e & 1) * 8;
        const int cg  = blockIdx.y;
        for (int idx = tid; idx < 6 * 34 * 32; idx += 256) {
            int cc  = idx / 204;
            int rem = idx - cc * 204;
            int row = rem / 34;
            int col = rem - row * 34;
            int gy = 4 * ty - 1 + row;
            int gx = 4 * txg - 1 + col;
            float v = 0.f;
            if (gy >= 0 && gy < 64 && gx >= 0 && gx < 64)
                v = q[((long)b * 256 + cg * 32 + cc) * 4096 + gy * 64 + gx];
            s[row][col][cc] = v;
        }
        __syncthreads();
        const int lane = tid & 31, w = tid >> 5;
        float d[6][6];
#pragma unroll
        for (int i = 0; i < 6; i++)
#pragma unroll
            for (int j = 0; j < 6; j++) d[i][j] = s[i][4 * w + j][lane];
        float t1[6][6];
#pragma unroll
        for (int j = 0; j < 6; j++) {
            t1[0][j] = 4.f * d[0][j] - 5.f * d[2][j] + d[4][j];
            t1[1][j] = -4.f * d[1][j] - 4.f * d[2][j] + d[3][j] + d[4][j];
            t1[2][j] =  4.f * d[1][j] - 4.f * d[2][j] - d[3][j] + d[4][j];
            t1[3][j] = -2.f * d[1][j] - d[2][j] + 2.f * d[3][j] + d[4][j];
            t1[4][j] =  2.f * d[1][j] - d[2][j] - 2.f * d[3][j] + d[4][j];
            t1[5][j] =  4.f * d[1][j] - 5.f * d[3][j] + d[5][j];
        }
        float V[6][6];
#pragma unroll
        for (int i = 0; i < 6; i++) {
            V[i][0] = 4.f * t1[i][0] - 5.f * t1[i][2] + t1[i][4];
            V[i][1] = -4.f * t1[i][1] - 4.f * t1[i][2] + t1[i][3] + t1[i][4];
            V[i][2] =  4.f * t1[i][1] - 4.f * t1[i][2] - t1[i][3] + t1[i][4];
            V[i][3] = -2.f * t1[i][1] - t1[i][2] + 2.f * t1[i][3] + t1[i][4];
            V[i][4] =  2.f * t1[i][1] - t1[i][2] - 2.f * t1[i][3] + t1[i][4];
            V[i][5] =  4.f * t1[i][1] - 5.f * t1[i][3] + t1[i][5];
        }
        const int tile = ty * 16 + txg + w;
#pragma unroll
        for (int i = 0; i < 6; i++)
#pragma unroll
            for (int j = 0; j < 6; j++) {
                int t = i * 6 + j;
                __half h, l;
                split_h(V[i][j], h, l);
                long base = ((long)(t * 4 + b) * NTILE + tile) * WROW + cg * 32 + lane;
                g_V[base] = h; g_V[base + 256] = l;
            }
    } else {
        const int bid = (((int)blockIdx.x - 202) * 8 + (int)blockIdx.y) * 4 + b;
        if (bid < 1024) {
            long i = (long)bid * 256 + tid;
            long l = i >> 16, rem = i & 65535;
            long o = rem >> 8, c = rem & 255;
            __half h, lo;
            split_h(vw[i], h, lo);
            long e = l * (256 * WROW) + o * WROW + c;
            g_vw[e] = h; g_vw[e + 256] = lo;
        } else if (bid < 1280) {
            long j = (long)(bid - 1024) * 256 + tid;
            long o = j >> 8, c = j & 255;
            __half h, lo;
            split_h(ow[j], h, lo);
            g_ow[o * WROW + c] = h; g_ow[o * WROW + c + 256] = lo;
        } else if (bid < 1536) {
            long j = (long)(bid - 1280) * 256 + tid;
            long c = j >> 8, m = j & 255;
            __half h, lo;
            split_h(qw[m * 256 + c], h, lo);
            g_qwT[c * WROW + m] = h; g_qwT[c * WROW + m + 256] = lo;
        } else if (bid < 1920) {
            const int o = bid - 1536;
            const int m = tid;
            const float* wsrc = (o < 256) ? offw + ((long)o * 256 + m) * 9
                                          : attw + ((long)(o - 256) * 256 + m) * 9;
            float w9[9];
#pragma unroll
            for (int k = 0; k < 9; k++) w9[k] = wsrc[k];
            float gw[6][3];
#pragma unroll
            for (int i = 0; i < 6; i++)
#pragma unroll
                for (int c = 0; c < 3; c++)
                    gw[i][c] = G6[i][0] * w9[c] + G6[i][1] * w9[3 + c] + G6[i][2] * w9[6 + c];
#pragma unroll
            for (int ti = 0; ti < 6; ti++)
#pragma unroll
                for (int tj = 0; tj < 6; tj++) {
                    float a = gw[ti][0] * G6[tj][0] + gw[ti][1] * G6[tj][1]
                            + gw[ti][2] * G6[tj][2];
                    __half h, lo;
                    split_h(a, h, lo);
                    long e = ((long)(ti * 6 + tj) * 384 + o) * WROW + m;
                    g_W2[e] = h; g_W2[e + 256] = lo;
                }
        } else if (bid == 1920) {
            if (tid < 384)
                g_cb[tid] = (tid < 256) ? offb[tid] : attb[tid - 256];
            if (tid < 256) {
                float sc = bg[tid] * rsqrtf(bv[tid] + BN_EPS);
                g_bns[tid] = sc;
                g_bnb[tid] = bb[tid] - bm[tid] * sc;
            }
        }
    }
}

// ---------------------------------------------------------------------------
// Fused F(4,3) output transform + sampling.
// Phase 2: lanes 0-15 precompute validity-folded weights + clamped offsets
// for their own (lvl,pt); gather loop = 8 shuffles + 4 ld + 4 fma per point.
// ---------------------------------------------------------------------------
__global__ __launch_bounds__(512)
void wgSample()
{
    __shared__ float scv[16][384];
    const int tile = blockIdx.x;
    const int b    = blockIdx.y;
    const int tid  = threadIdx.x;

    if (tid < 384) {
        const int oc = tid;
        const long tstr = (long)4 * NTILE * 384;
        const long base = ((long)b * NTILE + tile) * 384 + oc;
        float m[6][6];
#pragma unroll
        for (int t = 0; t < NT; t++)
            m[t / 6][t % 6] = g_M[(long)t * tstr + base];
        float tp[4][6];
#pragma unroll
        for (int j = 0; j < 6; j++) {
            tp[0][j] = m[0][j] + m[1][j] + m[2][j] + m[3][j] + m[4][j];
            tp[1][j] = m[1][j] - m[2][j] + 2.f * m[3][j] - 2.f * m[4][j];
            tp[2][j] = m[1][j] + m[2][j] + 4.f * m[3][j] + 4.f * m[4][j];
            tp[3][j] = m[1][j] - m[2][j] + 8.f * m[3][j] - 8.f * m[4][j] + m[5][j];
        }
        const float bs = g_cb[oc];
#pragma unroll
        for (int r = 0; r < 4; r++) {
            scv[r * 4 + 0][oc] = tp[r][0] + tp[r][1] + tp[r][2] + tp[r][3] + tp[r][4] + bs;
            scv[r * 4 + 1][oc] = tp[r][1] - tp[r][2] + 2.f * tp[r][3] - 2.f * tp[r][4] + bs;
            scv[r * 4 + 2][oc] = tp[r][1] + tp[r][2] + 4.f * tp[r][3] + 4.f * tp[r][4] + bs;
            scv[r * 4 + 3][oc] = tp[r][1] - tp[r][2] + 8.f * tp[r][3] - 8.f * tp[r][4] + tp[r][5] + bs;
        }
    }
    __syncthreads();

    const int warp = tid >> 5;
    const int lane = tid & 31;
    const int ty = tile >> 4, tx = tile & 15;
    const int pxl = warp;
    const int py  = 4 * ty + (pxl >> 2);
    const int px  = 4 * tx + (pxl & 3);
    const int pix = py * 64 + px;
    const float refx = -1.f + 2.f * (float)px / 63.f;
    const float refy = -1.f + 2.f * (float)py / 63.f;

    for (int h = 0; h < 8; h++) {
        // lanes 0..15: own (lvl,pt) = lane
        float lg = -INFINITY;
        float w00 = 0.f, w01 = 0.f, w10 = 0.f, w11 = 0.f;
        int o00 = 0, o01 = 0, o10 = 0, o11 = 0;
        float ox = 0.f, oy = 0.f;
        if (lane < 16) {
            lg = scv[pxl][256 + h * 16 + lane];
            ox = tanhf(scv[pxl][h * 32 + 2 * lane    ]) * 0.25f;
            oy = tanhf(scv[pxl][h * 32 + 2 * lane + 1]) * 0.25f;
        }
        float mx = lg;
#pragma unroll
        for (int s = 16; s > 0; s >>= 1)
            mx = fmaxf(mx, __shfl_xor_sync(0xFFFFFFFFu, mx, s));
        float e = (lane < 16) ? expf(lg - mx) : 0.f;
        float sum = e;
#pragma unroll
        for (int s = 16; s > 0; s >>= 1)
            sum += __shfl_xor_sync(0xFFFFFFFFu, sum, s);

        if (lane < 16) {
            const float aw  = e / sum;
            const int   lvl = lane >> 2;
            const int   sz  = 64 >> lvl;
            float xf = (refx + ox + 1.f) * 0.5f * (float)(sz - 1);
            float yf = (refy + oy + 1.f) * 0.5f * (float)(sz - 1);
            float x0f = floorf(xf), y0f = floorf(yf);
            int x0 = (int)x0f, y0 = (int)y0f;
            int x1 = x0 + 1,  y1 = y0 + 1;
            float wx1 = xf - x0f, wx0 = 1.f - wx1;
            float wy1 = yf - y0f, wy0 = 1.f - wy1;
            bool vx0 = (x0 >= 0) & (x0 < sz), vx1 = (x1 >= 0) & (x1 < sz);
            bool vy0 = (y0 >= 0) & (y0 < sz), vy1 = (y1 >= 0) & (y1 < sz);
            w00 = (vx0 & vy0) ? aw * wx0 * wy0 : 0.f;
            w01 = (vx1 & vy0) ? aw * wx1 * wy0 : 0.f;
            w10 = (vx0 & vy1) ? aw * wx0 * wy1 : 0.f;
            w11 = (vx1 & vy1) ? aw * wx1 * wy1 : 0.f;
            int xc0 = min(max(x0, 0), sz - 1), xc1 = min(max(x1, 0), sz - 1);
            int yc0 = min(max(y0, 0), sz - 1), yc1 = min(max(y1, 0), sz - 1);
            int base = c_voff[lvl];
            o00 = base + (yc0 * sz + xc0) * 256;
            o01 = base + (yc0 * sz + xc1) * 256;
            o10 = base + (yc1 * sz + xc0) * 256;
            o11 = base + (yc1 * sz + xc1) * 256;
        }

        const __half* vb = g_v + (long)b * VSTRF + h * 32 + lane;
        float acc = 0.f;
#pragma unroll
        for (int i = 0; i < 16; i++) {
            float a00 = __shfl_sync(0xFFFFFFFFu, w00, i);
            float a01 = __shfl_sync(0xFFFFFFFFu, w01, i);
            float a10 = __shfl_sync(0xFFFFFFFFu, w10, i);
            float a11 = __shfl_sync(0xFFFFFFFFu, w11, i);
            int   p00 = __shfl_sync(0xFFFFFFFFu, o00, i);
            int   p01 = __shfl_sync(0xFFFFFFFFu, o01, i);
            int   p10 = __shfl_sync(0xFFFFFFFFu, o10, i);
            int   p11 = __shfl_sync(0xFFFFFFFFu, o11, i);
            acc = fmaf(a00, __half2float(vb[p00]), acc);
            acc = fmaf(a01, __half2float(vb[p01]), acc);
            acc = fmaf(a10, __half2float(vb[p10]), acc);
            acc = fmaf(a11, __half2float(vb[p11]), acc);
        }

        g_att[((long)b * HW + pix) * AROW + h * 32 + lane] = __float2half_rn(acc);
    }
}

// ---------------------------------------------------------------------------
// Launch. wgSample is the 4th launch (ncu capture slot).
// ---------------------------------------------------------------------------
extern "C" void kernel_launch(void* const* d_in, const int* in_sizes, int n_in,
                              void* d_out, int out_size)
{
    const float* query  = (const float*)d_in[0];
    const float* feat0  = (const float*)d_in[1];
    const float* feat1  = (const float*)d_in[2];
    const float* feat2  = (const float*)d_in[3];
    const float* feat3  = (const float*)d_in[4];
    const float* q_w    = (const float*)d_in[5];
    const float* v_w    = (const float*)d_in[6];
    const float* out_w  = (const float*)d_in[7];
    const float* off_w  = (const float*)d_in[8];
    const float* off_b  = (const float*)d_in[9];
    const float* attn_w = (const float*)d_in[10];
    const float* attn_b = (const float*)d_in[11];
    const float* bn_g   = (const float*)d_in[12];
    const float* bn_b   = (const float*)d_in[13];
    const float* bn_m   = (const float*)d_in[14];
    const float* bn_v   = (const float*)d_in[15];
    float* out = (float*)d_out;

    cudaFuncSetAttribute(mm_all<0>, cudaFuncAttributeMaxDynamicSharedMemorySize, DSMEM_SZ);
    cudaFuncSetAttribute(mm_all<1>, cudaFuncAttributeMaxDynamicSharedMemorySize, DSMEM_SZ);
    cudaFuncSetAttribute(mm_all<3>, cudaFuncAttributeMaxDynamicSharedMemorySize, DSMEM_SZ);

    // 1. all prep: feat transposes + F(4,3) input transform + weight prep
    prepActs<<<dim3(263, 8, BATCH), 256>>>(query, feat0, feat1, feat2, feat3,
                                           q_w, v_w, out_w, off_w, attn_w,
                                           off_b, attn_b, bn_g, bn_b, bn_m, bn_v);

    // 2. compose winograd weights (3-term)
    mm_all<0><<<dim3(108, 2, 1), 256, DSMEM_SZ>>>(nullptr, nullptr);

    // 3. merged winograd (3-term) + vproj (2-term) GEMM
    mm_all<1><<<dim3(NT * 6 + 86, 1, BATCH), 256, DSMEM_SZ>>>(nullptr, nullptr);

    // 4. fused F(4,3) output transform + sampling   <-- ncu capture slot
    wgSample<<<dim3(NTILE, BATCH), 512>>>();

    // 5. output projection + residual + BN + SiLU (coalesced epilogue)
    mm_all<3><<<dim3(32, 2, BATCH), 256, DSMEM_SZ>>>(query, out);
}

// round 17
// speedup vs baseline: 1.5710x; 1.1770x over previous
#include <cuda_runtime.h>
#include <cuda_fp16.h>
#include <math.h>
#include <stdint.h>

// ---------------------------------------------------------------------------
// Problem constants
// ---------------------------------------------------------------------------
#define BATCH   4
#define HW      4096
#define BN_EPS  1e-5f
#define VPIX    5440
#define VSTRF   (VPIX*256)
#define WROW    512                  // split row: [256 hi][256 lo] fp16
#define AROW    256                  // plain activation row: 256 fp16
#define NT      36                   // winograd F(4,3): 6x6 transform points
#define NTILE   256                  // 16x16 tiles of 4x4 output per image

__device__ __constant__ int c_voff[4] = {0, 1048576, 1310720, 1376256};
__device__ __constant__ int c_vpix[4] = {0, 4096, 5120, 5376};
__device__ __constant__ int c_mact[4] = {4096, 1024, 256, 64};
__device__ __constant__ int c_vts[5]  = {0, 32, 40, 42, 43};
__device__ __constant__ int c_ftk[5]  = {0, 128, 160, 168, 170};
__constant__ float G6[6][3] = {
    {0.25f, 0.f, 0.f},
    {-1.f/6.f, -1.f/6.f, -1.f/6.f},
    {-1.f/6.f,  1.f/6.f, -1.f/6.f},
    {1.f/24.f,  1.f/12.f, 1.f/6.f},
    {1.f/24.f, -1.f/12.f, 1.f/6.f},
    {0.f, 0.f, 1.f}};

// ---------------------------------------------------------------------------
// Scratch
// ---------------------------------------------------------------------------
__device__ __half g_fT [BATCH * VPIX * AROW];      // feats fp16
__device__ __half g_att[BATCH * HW * AROW];        // sampler out fp16
__device__ __half g_qwT[256 * WROW];               // q_w^T split
__device__ __half g_vw [4 * 256 * WROW];           // v_w split
__device__ __half g_ow [256 * WROW];               // out_w split
__device__ __half g_W2 [NT * 384 * WROW];          // G-transformed conv w split
__device__ __half g_Uw [NT * 384 * WROW];          // winograd weights split
__device__ __half g_V  [(long)NT * 4 * NTILE * WROW]; // winograd input transform split
__device__ float g_M  [(long)NT * 4 * NTILE * 384];   // winograd GEMM out fp32
__device__ __half g_v  [BATCH * VSTRF];            // values fp16 channel-last
__device__ float g_cb [384];
__device__ float g_bns[256], g_bnb[256];

// ---------------------------------------------------------------------------
// Helpers
// ---------------------------------------------------------------------------
__device__ __forceinline__ uint32_t smem_u32(const void* p) {
    uint32_t a;
    asm("{ .reg .u64 t; cvta.to.shared.u64 t, %1; cvt.u32.u64 %0, t; }"
        : "=r"(a) : "l"(p));
    return a;
}
__device__ __forceinline__ void cp16(uint32_t dst, const void* src, bool v) {
    int sz = v ? 16 : 0;
    asm volatile("cp.async.cg.shared.global [%0], [%1], 16, %2;\n"
                 :: "r"(dst), "l"(src), "r"(sz) : "memory");
}
__device__ __forceinline__ void cp_commit() {
    asm volatile("cp.async.commit_group;\n" ::: "memory");
}
__device__ __forceinline__ void cp_wait1() {
    asm volatile("cp.async.wait_group 1;\n" ::: "memory");
}
__device__ __forceinline__ void mma_f16(float* c, const uint32_t* a, const uint32_t* b) {
    asm volatile(
        "mma.sync.aligned.m16n8k16.row.col.f32.f16.f16.f32 "
        "{%0,%1,%2,%3}, {%4,%5,%6,%7}, {%8,%9}, {%0,%1,%2,%3};"
        : "+f"(c[0]), "+f"(c[1]), "+f"(c[2]), "+f"(c[3])
        : "r"(a[0]), "r"(a[1]), "r"(a[2]), "r"(a[3]), "r"(b[0]), "r"(b[1]));
}
#define LDSM_X4(r0, r1, r2, r3, addr) \
    asm volatile("ldmatrix.sync.aligned.m8n8.x4.shared.b16 {%0,%1,%2,%3}, [%4];" \
        : "=r"(r0), "=r"(r1), "=r"(r2), "=r"(r3) : "r"(addr))

__device__ __forceinline__ void split_h(float x, __half& h, __half& l) {
    h = __float2half_rn(x);
    l = __float2half_rn(x - __half2float(h));
}
__device__ __forceinline__ float silu(float x) {
    return x / (1.f + expf(-x));
}

#define STG_B    16384
#define DSMEM_SZ (6 * STG_B)          // 96 KB -> 2 CTAs/SM

// ---------------------------------------------------------------------------
// Unified fp16 GEMM, K=256 (NK=8), D[128m][128n] = sum_k A[m][k]*B[n][k].
// LM 0: compose  (A split 3-term; rows 36*384)
// LM 1: merged winograd (A=V split, 3-term) + vproj (A=fT plain, 2-term)
// LM 3: outproj (+resid, BN, SiLU) with smem-staged coalesced epilogue
// ---------------------------------------------------------------------------
template<int LM>
__global__ __launch_bounds__(256, 2)
void mm_all(const float* __restrict__ resid, float* __restrict__ outp)
{
    extern __shared__ float sm[];

    const int b    = blockIdx.z;
    const int tid  = threadIdx.x;
    const int wid  = tid >> 5;
    const int lane = tid & 31;
    const int wm   = wid >> 2;
    const int wn   = wid & 3;
    const int gid  = lane >> 2;
    const int tig  = lane & 3;
    const int l8   = lane & 7;
    const int lm   = (lane >> 3) & 1;
    const int lh   = lane >> 4;

    // ---- per-CTA mode & geometry ----
    int mode, m0, n0, lvl = 0, M_act = 1 << 30;
    long mBase = 0;
    const __half *Abase, *Bbase;
    if (LM == 1) {
        int idx = blockIdx.x;
        if (idx < NT * 6) {
            mode = 1;
            int t = idx / 6, sub = idx % 6;
            m0 = (sub & 1) * 128; n0 = (sub >> 1) * 128;
            Abase = g_V + ((long)(t * 4 + b) * NTILE) * WROW;
            Bbase = g_Uw + (long)t * 384 * WROW;
            mBase = ((long)(t * 4 + b) * NTILE) * 384;
            M_act = NTILE;
        } else {
            mode = 2; int tv = idx - NT * 6;
            int nt = (tv >= 43) ? 1 : 0;
            int mtile = tv - nt * 43;
            while (mtile >= c_vts[lvl + 1]) lvl++;
            m0 = (mtile - c_vts[lvl]) * 128;
            n0 = nt * 128;
            M_act = c_mact[lvl];
            Abase = g_fT + (long)b * VPIX * AROW + (long)c_vpix[lvl] * AROW;
            Bbase = g_vw + lvl * 256 * WROW;
        }
    } else if (LM == 0) {
        mode = 0; m0 = blockIdx.x * 128; n0 = blockIdx.y * 128;
        Abase = g_W2; Bbase = g_qwT;
        M_act = NT * 384;
    } else {
        mode = 3; m0 = blockIdx.x * 128; n0 = blockIdx.y * 128;
        Abase = g_att + (long)b * HW * AROW; Bbase = g_ow;
        M_act = 4096;
    }
    const bool splitA = (LM == 0) || (LM == 1 && mode == 1);

    // ---- hoisted loader state ----
    const int r0    = tid >> 3;
    const int sub   = tid & 7;
    const int plane = sub >> 2;
    const int kc    = sub & 3;
    const int phys  = sub ^ (r0 & 7);
    const uint32_t smb = smem_u32(sm);

    const __half* aBW = Abase + (long)(m0 + r0) * WROW + plane * 256 + kc * 8;
    const __half* aBA = Abase + (long)(m0 + r0) * AROW + sub * 8;
    const __half* bP  = Bbase + (long)(n0 + r0) * WROW + plane * 256 + kc * 8;
    const uint32_t dA0 = smb + r0 * 128 + phys * 16;
    const uint32_t dB0 = dA0 + 3 * STG_B;

    bool aOK[4];
#pragma unroll
    for (int i = 0; i < 4; i++) aOK[i] = (m0 + r0 + 32 * i) < M_act;

    float acc[4][4][4];
#pragma unroll
    for (int mt = 0; mt < 4; mt++)
#pragma unroll
        for (int nt = 0; nt < 4; nt++)
#pragma unroll
            for (int r = 0; r < 4; r++) acc[mt][nt][r] = 0.f;

    auto load_stage = [&](int s, int buf) {
        const __half* bp = bP + s * 32;
        const uint32_t dB = dB0 + buf * STG_B;
#pragma unroll
        for (int i = 0; i < 4; i++)
            cp16(dB + i * 4096, bp + i * 32 * WROW, true);
        const uint32_t dA = dA0 + buf * STG_B;
        if (splitA) {
            const __half* ap = aBW + s * 32;
#pragma unroll
            for (int i = 0; i < 4; i++)
                cp16(dA + i * 4096, aOK[i] ? (ap + i * 32 * WROW) : (const void*)Abase, aOK[i]);
        } else if (sub < 4) {
            const __half* ap = aBA + s * 32;
#pragma unroll
            for (int i = 0; i < 4; i++)
                cp16(dA + i * 4096, aOK[i] ? (ap + i * 32 * AROW) : (const void*)Abase, aOK[i]);
        }
    };

    load_stage(0, 0); cp_commit();
    load_stage(1, 1); cp_commit();

    for (int s = 0; s < 8; s++) {
        const int buf = s % 3;
        cp_wait1();
        __syncthreads();
        if (s + 2 < 8) { load_stage(s + 2, (s + 2) % 3); }
        cp_commit();

        const uint32_t aBase_s = smb + buf * STG_B;
        const uint32_t bBase_s = smb + (3 + buf) * STG_B;
#pragma unroll
        for (int kk = 0; kk < 2; kk++) {
            const int chH = kk * 2 + lh;
            const int chL = chH + 4;
            uint32_t ah[4][4], al[4][4], bh[4][2], bl[4][2];
#pragma unroll
            for (int mt = 0; mt < 4; mt++) {
                int row = wm * 64 + mt * 16 + l8 + lm * 8;
                uint32_t base = aBase_s + row * 128;
                LDSM_X4(ah[mt][0], ah[mt][1], ah[mt][2], ah[mt][3],
                        base + ((chH ^ l8) << 4));
                if (splitA)
                    LDSM_X4(al[mt][0], al[mt][1], al[mt][2], al[mt][3],
                            base + ((chL ^ l8) << 4));
            }
#pragma unroll
            for (int np = 0; np < 2; np++) {
                int row = wn * 32 + np * 16 + l8 + lm * 8;
                uint32_t base = bBase_s + row * 128;
                LDSM_X4(bh[2 * np][0], bh[2 * np + 1][0],
                        bh[2 * np][1], bh[2 * np + 1][1],
                        base + ((chH ^ l8) << 4));
                LDSM_X4(bl[2 * np][0], bl[2 * np + 1][0],
                        bl[2 * np][1], bl[2 * np + 1][1],
                        base + ((chL ^ l8) << 4));
            }
            if (splitA) {
#pragma unroll
                for (int mt = 0; mt < 4; mt++)
#pragma unroll
                    for (int nt = 0; nt < 4; nt++) {
                        mma_f16(acc[mt][nt], ah[mt], bh[nt]);
                        mma_f16(acc[mt][nt], ah[mt], bl[nt]);
                        mma_f16(acc[mt][nt], al[mt], bh[nt]);
                    }
            } else {
#pragma unroll
                for (int mt = 0; mt < 4; mt++)
#pragma unroll
                    for (int nt = 0; nt < 4; nt++) {
                        mma_f16(acc[mt][nt], ah[mt], bh[nt]);
                        mma_f16(acc[mt][nt], ah[mt], bl[nt]);
                    }
            }
        }
    }

    // ---- epilogues ----
    if (LM != 3) {
#pragma unroll
        for (int mt = 0; mt < 4; mt++) {
            int r0e = m0 + wm * 64 + mt * 16 + gid;
#pragma unroll
            for (int nt = 0; nt < 4; nt++) {
                int col = n0 + wn * 32 + nt * 8 + tig * 2;
#pragma unroll
                for (int h = 0; h < 2; h++) {
                    int r = r0e + h * 8;
                    float vx = acc[mt][nt][2 * h];
                    float vy = acc[mt][nt][2 * h + 1];
                    if (mode == 0) {
                        long e = (long)r * WROW + col;
                        __half hh, ll;
                        split_h(vx, hh, ll); g_Uw[e]     = hh; g_Uw[e + 256]     = ll;
                        split_h(vy, hh, ll); g_Uw[e + 1] = hh; g_Uw[e + 1 + 256] = ll;
                    } else if (mode == 1) {
                        if (r < M_act)
                            *(float2*)&g_M[mBase + (long)r * 384 + col] = make_float2(vx, vy);
                    } else {
                        if (r < M_act) {
                            long row = c_vpix[lvl] + r;
                            *(__half2*)&g_v[(long)b * VSTRF + row * 256 + col] =
                                __floats2half2_rn(vx, vy);
                        }
                    }
                }
            }
        }
    } else {
        __syncthreads();
        float* sf = sm;
#pragma unroll
        for (int mt = 0; mt < 4; mt++) {
            int rl0 = wm * 64 + mt * 16 + gid;
#pragma unroll
            for (int nt = 0; nt < 4; nt++) {
                int cl = wn * 32 + nt * 8 + tig * 2;
#pragma unroll
                for (int h = 0; h < 2; h++) {
                    int rl = rl0 + h * 8;
                    sf[(cl)     * 132 + rl] = acc[mt][nt][2 * h];
                    sf[(cl + 1) * 132 + rl] = acc[mt][nt][2 * h + 1];
                }
            }
        }
        __syncthreads();
        const float* qb = resid + (long)b * 256 * HW;
        float* yb = outp + (long)b * 256 * HW;
        for (int i = tid; i < 128 * 32; i += 256) {
            int ocl = i >> 5;
            int r4  = i & 31;
            int oc  = n0 + ocl;
            int rg  = m0 + r4 * 4;
            float4 qv = *(const float4*)&qb[(long)oc * HW + rg];
            float4 o;
            o.x = silu((sf[ocl * 132 + r4 * 4 + 0] + qv.x) * g_bns[oc] + g_bnb[oc]);
            o.y = silu((sf[ocl * 132 + r4 * 4 + 1] + qv.y) * g_bns[oc] + g_bnb[oc]);
            o.z = silu((sf[ocl * 132 + r4 * 4 + 2] + qv.z) * g_bns[oc] + g_bnb[oc]);
            o.w = silu((sf[ocl * 132 + r4 * 4 + 3] + qv.w) * g_bns[oc] + g_bnb[oc]);
            *(float4*)&yb[(long)oc * HW + rg] = o;
        }
    }
}

// ---------------------------------------------------------------------------
// Merged prep: feat transposes + F(4,3) input transform + weight prep.
// ---------------------------------------------------------------------------
__global__ __launch_bounds__(256)
void prepActs(const float* __restrict__ q,
              const float* __restrict__ f0, const float* __restrict__ f1,
              const float* __restrict__ f2, const float* __restrict__ f3,
              const float* __restrict__ qw, const float* __restrict__ vw,
              const float* __restrict__ ow,
              const float* __restrict__ offw, const float* __restrict__ attw,
              const float* __restrict__ offb, const float* __restrict__ attb,
              const float* __restrict__ bg, const float* __restrict__ bb,
              const float* __restrict__ bm, const float* __restrict__ bv)
{
    __shared__ float tbuf[32][33];
    __shared__ float s[6][34][32];
    const int b = blockIdx.z;
    const int tid = threadIdx.x;

    if (blockIdx.x < 170) {
        int lvl = 0;
        while ((int)blockIdx.x >= c_ftk[lvl + 1]) lvl++;
        const int P  = c_mact[lvl];
        const int p0 = (blockIdx.x - c_ftk[lvl]) * 32;
        const float* I = (lvl == 0 ? f0 : lvl == 1 ? f1 : lvl == 2 ? f2 : f3)
                       + (long)b * 256 * P;
        __half* Of = g_fT + (long)b * VPIX * AROW + (long)c_vpix[lvl] * AROW;
        const int c0 = blockIdx.y * 32;
        const int tx = tid & 31, ty = tid >> 5;
#pragma unroll
        for (int i = 0; i < 32; i += 8)
            tbuf[ty + i][tx] = I[(long)(c0 + ty + i) * P + p0 + tx];
        __syncthreads();
#pragma unroll
        for (int i = 0; i < 32; i += 8)
            Of[(long)(p0 + ty + i) * AROW + c0 + tx] = __float2half_rn(tbuf[tx][ty + i]);
    } else if (blockIdx.x < 202) {
        const int e   = blockIdx.x - 170;
        const int ty  = e >> 1;
        const int txg = (e & 1) * 8;
        const int cg  = blockIdx.y;
        for (int idx = tid; idx < 6 * 34 * 32; idx += 256) {
            int cc  = idx / 204;
            int rem = idx - cc * 204;
            int row = rem / 34;
            int col = rem - row * 34;
            int gy = 4 * ty - 1 + row;
            int gx = 4 * txg - 1 + col;
            float v = 0.f;
            if (gy >= 0 && gy < 64 && gx >= 0 && gx < 64)
                v = q[((long)b * 256 + cg * 32 + cc) * 4096 + gy * 64 + gx];
            s[row][col][cc] = v;
        }
        __syncthreads();
        const int lane = tid & 31, w = tid >> 5;
        float d[6][6];
#pragma unroll
        for (int i = 0; i < 6; i++)
#pragma unroll
            for (int j = 0; j < 6; j++) d[i][j] = s[i][4 * w + j][lane];
        float t1[6][6];
#pragma unroll
        for (int j = 0; j < 6; j++) {
            t1[0][j] = 4.f * d[0][j] - 5.f * d[2][j] + d[4][j];
            t1[1][j] = -4.f * d[1][j] - 4.f * d[2][j] + d[3][j] + d[4][j];
            t1[2][j] =  4.f * d[1][j] - 4.f * d[2][j] - d[3][j] + d[4][j];
            t1[3][j] = -2.f * d[1][j] - d[2][j] + 2.f * d[3][j] + d[4][j];
            t1[4][j] =  2.f * d[1][j] - d[2][j] - 2.f * d[3][j] + d[4][j];
            t1[5][j] =  4.f * d[1][j] - 5.f * d[3][j] + d[5][j];
        }
        float V[6][6];
#pragma unroll
        for (int i = 0; i < 6; i++) {
            V[i][0] = 4.f * t1[i][0] - 5.f * t1[i][2] + t1[i][4];
            V[i][1] = -4.f * t1[i][1] - 4.f * t1[i][2] + t1[i][3] + t1[i][4];
            V[i][2] =  4.f * t1[i][1] - 4.f * t1[i][2] - t1[i][3] + t1[i][4];
            V[i][3] = -2.f * t1[i][1] - t1[i][2] + 2.f * t1[i][3] + t1[i][4];
            V[i][4] =  2.f * t1[i][1] - t1[i][2] - 2.f * t1[i][3] + t1[i][4];
            V[i][5] =  4.f * t1[i][1] - 5.f * t1[i][3] + t1[i][5];
        }
        const int tile = ty * 16 + txg + w;
#pragma unroll
        for (int i = 0; i < 6; i++)
#pragma unroll
            for (int j = 0; j < 6; j++) {
                int t = i * 6 + j;
                __half h, l;
                split_h(V[i][j], h, l);
                long base = ((long)(t * 4 + b) * NTILE + tile) * WROW + cg * 32 + lane;
                g_V[base] = h; g_V[base + 256] = l;
            }
    } else {
        const int bid = (((int)blockIdx.x - 202) * 8 + (int)blockIdx.y) * 4 + b;
        if (bid < 1024) {
            long i = (long)bid * 256 + tid;
            long l = i >> 16, rem = i & 65535;
            long o = rem >> 8, c = rem & 255;
            __half h, lo;
            split_h(vw[i], h, lo);
            long e = l * (256 * WROW) + o * WROW + c;
            g_vw[e] = h; g_vw[e + 256] = lo;
        } else if (bid < 1280) {
            long j = (long)(bid - 1024) * 256 + tid;
            long o = j >> 8, c = j & 255;
            __half h, lo;
            split_h(ow[j], h, lo);
            g_ow[o * WROW + c] = h; g_ow[o * WROW + c + 256] = lo;
        } else if (bid < 1536) {
            long j = (long)(bid - 1280) * 256 + tid;
            long c = j >> 8, m = j & 255;
            __half h, lo;
            split_h(qw[m * 256 + c], h, lo);
            g_qwT[c * WROW + m] = h; g_qwT[c * WROW + m + 256] = lo;
        } else if (bid < 1920) {
            const int o = bid - 1536;
            const int m = tid;
            const float* wsrc = (o < 256) ? offw + ((long)o * 256 + m) * 9
                                          : attw + ((long)(o - 256) * 256 + m) * 9;
            float w9[9];
#pragma unroll
            for (int k = 0; k < 9; k++) w9[k] = wsrc[k];
            float gw[6][3];
#pragma unroll
            for (int i = 0; i < 6; i++)
#pragma unroll
                for (int c = 0; c < 3; c++)
                    gw[i][c] = G6[i][0] * w9[c] + G6[i][1] * w9[3 + c] + G6[i][2] * w9[6 + c];
#pragma unroll
            for (int ti = 0; ti < 6; ti++)
#pragma unroll
                for (int tj = 0; tj < 6; tj++) {
                    float a = gw[ti][0] * G6[tj][0] + gw[ti][1] * G6[tj][1]
                            + gw[ti][2] * G6[tj][2];
                    __half h, lo;
                    split_h(a, h, lo);
                    long e = ((long)(ti * 6 + tj) * 384 + o) * WROW + m;
                    g_W2[e] = h; g_W2[e + 256] = lo;
                }
        } else if (bid == 1920) {
            if (tid < 384)
                g_cb[tid] = (tid < 256) ? offb[tid] : attb[tid - 256];
            if (tid < 256) {
                float sc = bg[tid] * rsqrtf(bv[tid] + BN_EPS);
                g_bns[tid] = sc;
                g_bnb[tid] = bb[tid] - bm[tid] * sc;
            }
        }
    }
}

// ---------------------------------------------------------------------------
// Fused F(4,3) output transform + sampling with head-pairing.
// Phase 2: half-warp = one head of a pair. Lane (hl = lane&15) owns
// (lvl,pt) hl for its head; gather loads __half2 channel pairs.
// ---------------------------------------------------------------------------
__global__ __launch_bounds__(512)
void wgSample()
{
    __shared__ float scv[16][384];
    const int tile = blockIdx.x;
    const int b    = blockIdx.y;
    const int tid  = threadIdx.x;

    if (tid < 384) {
        const int oc = tid;
        const long tstr = (long)4 * NTILE * 384;
        const long base = ((long)b * NTILE + tile) * 384 + oc;
        float m[6][6];
#pragma unroll
        for (int t = 0; t < NT; t++)
            m[t / 6][t % 6] = g_M[(long)t * tstr + base];
        float tp[4][6];
#pragma unroll
        for (int j = 0; j < 6; j++) {
            tp[0][j] = m[0][j] + m[1][j] + m[2][j] + m[3][j] + m[4][j];
            tp[1][j] = m[1][j] - m[2][j] + 2.f * m[3][j] - 2.f * m[4][j];
            tp[2][j] = m[1][j] + m[2][j] + 4.f * m[3][j] + 4.f * m[4][j];
            tp[3][j] = m[1][j] - m[2][j] + 8.f * m[3][j] - 8.f * m[4][j] + m[5][j];
        }
        const float bs = g_cb[oc];
#pragma unroll
        for (int r = 0; r < 4; r++) {
            scv[r * 4 + 0][oc] = tp[r][0] + tp[r][1] + tp[r][2] + tp[r][3] + tp[r][4] + bs;
            scv[r * 4 + 1][oc] = tp[r][1] - tp[r][2] + 2.f * tp[r][3] - 2.f * tp[r][4] + bs;
            scv[r * 4 + 2][oc] = tp[r][1] + tp[r][2] + 4.f * tp[r][3] + 4.f * tp[r][4] + bs;
            scv[r * 4 + 3][oc] = tp[r][1] - tp[r][2] + 8.f * tp[r][3] - 8.f * tp[r][4] + tp[r][5] + bs;
        }
    }
    __syncthreads();

    const int warp = tid >> 5;
    const int lane = tid & 31;
    const int hl   = lane & 15;          // point id / channel-pair id
    const int hhi  = lane >> 4;          // which head of the pair
    const int ty = tile >> 4, tx = tile & 15;
    const int pxl = warp;
    const int py  = 4 * ty + (pxl >> 2);
    const int px  = 4 * tx + (pxl & 3);
    const int pix = py * 64 + px;
    const float refx = -1.f + 2.f * (float)px / 63.f;
    const float refy = -1.f + 2.f * (float)py / 63.f;

    for (int hp = 0; hp < 4; hp++) {
        const int h = 2 * hp + hhi;

        // every lane: precompute for its own (lvl,pt)=hl of head h
        float lg = scv[pxl][256 + h * 16 + hl];
        float ox = tanhf(scv[pxl][h * 32 + 2 * hl    ]) * 0.25f;
        float oy = tanhf(scv[pxl][h * 32 + 2 * hl + 1]) * 0.25f;

        // softmax within the 16-lane half-warp group
        float mx = lg;
#pragma unroll
        for (int s = 8; s > 0; s >>= 1)
            mx = fmaxf(mx, __shfl_xor_sync(0xFFFFFFFFu, mx, s));
        float e = expf(lg - mx);
        float sum = e;
#pragma unroll
        for (int s = 8; s > 0; s >>= 1)
            sum += __shfl_xor_sync(0xFFFFFFFFu, sum, s);

        const float aw  = e / sum;
        const int   lvl = hl >> 2;
        const int   sz  = 64 >> lvl;
        float xf = (refx + ox + 1.f) * 0.5f * (float)(sz - 1);
        float yf = (refy + oy + 1.f) * 0.5f * (float)(sz - 1);
        float x0f = floorf(xf), y0f = floorf(yf);
        int x0 = (int)x0f, y0 = (int)y0f;
        int x1 = x0 + 1,  y1 = y0 + 1;
        float wx1 = xf - x0f, wx0 = 1.f - wx1;
        float wy1 = yf - y0f, wy0 = 1.f - wy1;
        bool vx0 = (x0 >= 0) & (x0 < sz), vx1 = (x1 >= 0) & (x1 < sz);
        bool vy0 = (y0 >= 0) & (y0 < sz), vy1 = (y1 >= 0) & (y1 < sz);
        float w00 = (vx0 & vy0) ? aw * wx0 * wy0 : 0.f;
        float w01 = (vx1 & vy0) ? aw * wx1 * wy0 : 0.f;
        float w10 = (vx0 & vy1) ? aw * wx0 * wy1 : 0.f;
        float w11 = (vx1 & vy1) ? aw * wx1 * wy1 : 0.f;
        int xc0 = min(max(x0, 0), sz - 1), xc1 = min(max(x1, 0), sz - 1);
        int yc0 = min(max(y0, 0), sz - 1), yc1 = min(max(y1, 0), sz - 1);
        int vbase = c_voff[lvl];
        int o00 = vbase + (yc0 * sz + xc0) * 256;
        int o01 = vbase + (yc0 * sz + xc1) * 256;
        int o10 = vbase + (yc1 * sz + xc0) * 256;
        int o11 = vbase + (yc1 * sz + xc1) * 256;

        // gather: lane covers channels (2*hl, 2*hl+1) of head h via half2
        const __half* vb = g_v + (long)b * VSTRF + h * 32 + 2 * hl;
        float accx = 0.f, accy = 0.f;
        const int sbase = lane & 16;     // shuffle from own half-warp
#pragma unroll
        for (int i = 0; i < 16; i++) {
            const int src = sbase + i;
            float a00 = __shfl_sync(0xFFFFFFFFu, w00, src);
            float a01 = __shfl_sync(0xFFFFFFFFu, w01, src);
            float a10 = __shfl_sync(0xFFFFFFFFu, w10, src);
            float a11 = __shfl_sync(0xFFFFFFFFu, w11, src);
            int   p00 = __shfl_sync(0xFFFFFFFFu, o00, src);
            int   p01 = __shfl_sync(0xFFFFFFFFu, o01, src);
            int   p10 = __shfl_sync(0xFFFFFFFFu, o10, src);
            int   p11 = __shfl_sync(0xFFFFFFFFu, o11, src);
            float2 f00 = __half22float2(*(const __half2*)(vb + p00));
            float2 f01 = __half22float2(*(const __half2*)(vb + p01));
            float2 f10 = __half22float2(*(const __half2*)(vb + p10));
            float2 f11 = __half22float2(*(const __half2*)(vb + p11));
            accx = fmaf(a00, f00.x, accx); accy = fmaf(a00, f00.y, accy);
            accx = fmaf(a01, f01.x, accx); accy = fmaf(a01, f01.y, accy);
            accx = fmaf(a10, f10.x, accx); accy = fmaf(a10, f10.y, accy);
            accx = fmaf(a11, f11.x, accx); accy = fmaf(a11, f11.y, accy);
        }

        *(__half2*)&g_att[((long)b * HW + pix) * AROW + h * 32 + 2 * hl] =
            __floats2half2_rn(accx, accy);
    }
}

// ---------------------------------------------------------------------------
// Launch. wgSample is the 4th launch (ncu capture slot).
// ---------------------------------------------------------------------------
extern "C" void kernel_launch(void* const* d_in, const int* in_sizes, int n_in,
                              void* d_out, int out_size)
{
    const float* query  = (const float*)d_in[0];
    const float* feat0  = (const float*)d_in[1];
    const float* feat1  = (const float*)d_in[2];
    const float* feat2  = (const float*)d_in[3];
    const float* feat3  = (const float*)d_in[4];
    const float* q_w    = (const float*)d_in[5];
    const float* v_w    = (const float*)d_in[6];
    const float* out_w  = (const float*)d_in[7];
    const float* off_w  = (const float*)d_in[8];
    const float* off_b  = (const float*)d_in[9];
    const float* attn_w = (const float*)d_in[10];
    const float* attn_b = (const float*)d_in[11];
    const float* bn_g   = (const float*)d_in[12];
    const float* bn_b   = (const float*)d_in[13];
    const float* bn_m   = (const float*)d_in[14];
    const float* bn_v   = (const float*)d_in[15];
    float* out = (float*)d_out;

    cudaFuncSetAttribute(mm_all<0>, cudaFuncAttributeMaxDynamicSharedMemorySize, DSMEM_SZ);
    cudaFuncSetAttribute(mm_all<1>, cudaFuncAttributeMaxDynamicSharedMemorySize, DSMEM_SZ);
    cudaFuncSetAttribute(mm_all<3>, cudaFuncAttributeMaxDynamicSharedMemorySize, DSMEM_SZ);

    // 1. all prep: feat transposes + F(4,3) input transform + weight prep
    prepActs<<<dim3(263, 8, BATCH), 256>>>(query, feat0, feat1, feat2, feat3,
                                           q_w, v_w, out_w, off_w, attn_w,
                                           off_b, attn_b, bn_g, bn_b, bn_m, bn_v);

    // 2. compose winograd weights (3-term)
    mm_all<0><<<dim3(108, 2, 1), 256, DSMEM_SZ>>>(nullptr, nullptr);

    // 3. merged winograd (3-term) + vproj (2-term) GEMM
    mm_all<1><<<dim3(NT * 6 + 86, 1, BATCH), 256, DSMEM_SZ>>>(nullptr, nullptr);

    // 4. fused F(4,3) output transform + sampling   <-- ncu capture slot
    wgSample<<<dim3(NTILE, BATCH), 512>>>();

    // 5. output projection + residual + BN + SiLU (coalesced epilogue)
    mm_all<3><<<dim3(32, 2, BATCH), 256, DSMEM_SZ>>>(query, out);
}